// round 6
// baseline (speedup 1.0000x reference)
#include <cuda_runtime.h>
#include <cuda_bf16.h>
#include <cstdint>
#include <cstddef>

#define NN   8192
#define HID  192
#define INF  256
#define MAXN 128

// ---------------- device scratch ----------------
__device__ float g_supA[NN * HID];
__device__ float g_supB[NN * HID];
__device__ float g_featbuf[NN * HID];
__device__ float g_sup3[NN * 3];
__device__ __nv_bfloat16 g_xhi[NN * INF];
__device__ __nv_bfloat16 g_xlo[NN * INF];
#define WT_TOTAL (192*256 + 12*192*192)
__device__ __nv_bfloat16 g_wthi[WT_TOTAL];
__device__ __nv_bfloat16 g_wtlo[WT_TOTAL];
__device__ int   g_nidx[NN * MAXN];
__device__ float g_nval[NN * MAXN];
__device__ int   g_ncnt[NN];

// ---------------- PTX helpers (compute_103-safe) ----------------
__device__ __forceinline__ uint32_t smem_u32(const void* p) {
    uint32_t a;
    asm("{ .reg .u64 t; cvta.to.shared.u64 t, %1; cvt.u32.u64 %0, t; }" : "=r"(a) : "l"(p));
    return a;
}
__device__ __forceinline__ void cp16(uint32_t d, const void* s) {
    asm volatile("cp.async.cg.shared.global [%0], [%1], 16;" :: "r"(d), "l"(s));
}
__device__ __forceinline__ void cp_commit() {
    asm volatile("cp.async.commit_group;" ::: "memory");
}
__device__ __forceinline__ void cp_wait_all() {
    asm volatile("cp.async.wait_all;" ::: "memory");
}
__device__ __forceinline__ void ldmx4(uint32_t* r, uint32_t a) {
    asm volatile("ldmatrix.sync.aligned.m8n8.x4.shared.b16 {%0,%1,%2,%3}, [%4];"
        : "=r"(r[0]), "=r"(r[1]), "=r"(r[2]), "=r"(r[3]) : "r"(a));
}
__device__ __forceinline__ void mma16816(float* d, const uint32_t* a, const uint32_t* b) {
    asm volatile("mma.sync.aligned.m16n8k16.row.col.f32.bf16.bf16.f32 "
        "{%0,%1,%2,%3}, {%4,%5,%6,%7}, {%8,%9}, {%0,%1,%2,%3};"
        : "+f"(d[0]), "+f"(d[1]), "+f"(d[2]), "+f"(d[3])
        : "r"(a[0]), "r"(a[1]), "r"(a[2]), "r"(a[3]), "r"(b[0]), "r"(b[1]));
}

// ---------------- CSR extraction (pads each row to multiple of 4) ----------------
__global__ __launch_bounds__(256) void build_csr(const float* __restrict__ adj,
                                                 int* __restrict__ nidx,
                                                 float* __restrict__ nval,
                                                 int* __restrict__ ncnt)
{
    int warp = (blockIdx.x * blockDim.x + threadIdx.x) >> 5;
    int lane = threadIdx.x & 31;
    if (warp >= NN) return;
    const float4* row = reinterpret_cast<const float4*>(adj + (size_t)warp * NN);
    int* my_idx = nidx + (size_t)warp * MAXN;
    float* my_val = nval + (size_t)warp * MAXN;
    int count = 0;
    for (int it = 0; it < NN / 128; it++) {
        float4 v = row[it * 32 + lane];
        int c0 = it * 128 + lane * 4;
        int my = (v.x != 0.f) + (v.y != 0.f) + (v.z != 0.f) + (v.w != 0.f);
        int inc = my;
        #pragma unroll
        for (int d = 1; d < 32; d <<= 1) {
            int t = __shfl_up_sync(0xffffffffu, inc, d);
            if (lane >= d) inc += t;
        }
        int total = __shfl_sync(0xffffffffu, inc, 31);
        int pos = count + inc - my;
        if (v.x != 0.f) { if (pos < MAXN) { my_idx[pos] = c0;     my_val[pos] = v.x; } pos++; }
        if (v.y != 0.f) { if (pos < MAXN) { my_idx[pos] = c0 + 1; my_val[pos] = v.y; } pos++; }
        if (v.z != 0.f) { if (pos < MAXN) { my_idx[pos] = c0 + 2; my_val[pos] = v.z; } pos++; }
        if (v.w != 0.f) { if (pos < MAXN) { my_idx[pos] = c0 + 3; my_val[pos] = v.w; } pos++; }
        count += total;
    }
    if (count > MAXN) count = MAXN;
    int padded = (count + 3) & ~3;
    if (padded > MAXN) padded = MAXN;
    for (int s = count + lane; s < padded; s += 32) { my_idx[s] = 0; my_val[s] = 0.f; }
    if (lane == 0) ncnt[warp] = padded;
}

// ---------------- weight / feature conversion ----------------
__global__ __launch_bounds__(256) void convert_weights(const float* __restrict__ W1,
                                                       const float* __restrict__ W_mid,
                                                       __nv_bfloat16* __restrict__ whi,
                                                       __nv_bfloat16* __restrict__ wlo)
{
    int idx = blockIdx.x * blockDim.x + threadIdx.x;
    if (idx >= WT_TOTAL) return;
    float w;
    if (idx < 192 * 256) {
        int n = idx / 256, k = idx % 256;
        w = W1[k * 192 + n];
    } else {
        int rel = idx - 192 * 256;
        int i = rel / (192 * 192);
        int r = rel % (192 * 192);
        int n = r / 192, k = r % 192;
        w = W_mid[(size_t)i * 192 * 192 + k * 192 + n];
    }
    __nv_bfloat16 h = __float2bfloat16(w);
    whi[idx] = h;
    wlo[idx] = __float2bfloat16(w - __bfloat162float(h));
}

__global__ __launch_bounds__(256) void convert_features(const float* __restrict__ f,
                                                        __nv_bfloat16* __restrict__ xhi,
                                                        __nv_bfloat16* __restrict__ xlo)
{
    int idx = blockIdx.x * blockDim.x + threadIdx.x;
    if (idx >= NN * INF) return;
    float v = f[idx];
    __nv_bfloat16 h = __float2bfloat16(v);
    xhi[idx] = h;
    xlo[idx] = __float2bfloat16(v - __bfloat162float(h));
}

// ---------------- gc1: one-shot split-bf16 HMMA GEMM, K=256 ----------------
#define BM 64
#define BN 64
template <int KK>
__global__ void __launch_bounds__(256, 1)
gemm_os(const __nv_bfloat16* __restrict__ Xh, const __nv_bfloat16* __restrict__ Xl,
        const __nv_bfloat16* __restrict__ Wh, const __nv_bfloat16* __restrict__ Wl,
        float* __restrict__ S)
{
    constexpr int ASTR = KK * 2 + 16;
    constexpr int SLAB = BM * ASTR;
    constexpr int SEGS = KK / 8;
    extern __shared__ char smem[];
    uint32_t sb = smem_u32(smem);
    const uint32_t sAH = sb, sAL = sb + SLAB, sBH = sb + 2 * SLAB, sBL = sb + 3 * SLAB;

    int tid = threadIdx.x;
    int m0 = blockIdx.x * BM;
    int n0 = blockIdx.y * BN;
    int w = tid >> 5, lane = tid & 31;
    int wm = (w & 3) * 16;
    int wn = (w >> 2) * 32;

    #pragma unroll
    for (int v = tid; v < BM * SEGS; v += 256) {
        int row = v / SEGS, seg = v % SEGS;
        uint32_t so = row * ASTR + seg * 16;
        size_t ga = (size_t)(m0 + row) * KK + seg * 8;
        size_t gb = (size_t)(n0 + row) * KK + seg * 8;
        cp16(sAH + so, Xh + ga);
        cp16(sAL + so, Xl + ga);
        cp16(sBH + so, Wh + gb);
        cp16(sBL + so, Wl + gb);
    }
    cp_commit();

    float acc[4][4];
    #pragma unroll
    for (int nt = 0; nt < 4; nt++)
        #pragma unroll
        for (int q = 0; q < 4; q++) acc[nt][q] = 0.f;

    cp_wait_all();
    __syncthreads();

    uint32_t aoff = (wm + (lane & 15)) * ASTR + (lane >> 4) * 16;
    uint32_t boff0 = (wn + (lane & 7) + ((lane >> 4) << 3)) * ASTR + (((lane >> 3) & 1) * 16);
    uint32_t boff1 = boff0 + 16 * ASTR;

    #pragma unroll
    for (int ks = 0; ks < KK / 16; ks++) {
        uint32_t ko = ks * 32;
        uint32_t ah[4], al[4], bh[2][4], bl[2][4];
        ldmx4(ah, sAH + aoff + ko);
        ldmx4(al, sAL + aoff + ko);
        ldmx4(bh[0], sBH + boff0 + ko);
        ldmx4(bl[0], sBL + boff0 + ko);
        ldmx4(bh[1], sBH + boff1 + ko);
        ldmx4(bl[1], sBL + boff1 + ko);
        #pragma unroll
        for (int nt = 0; nt < 4; nt++) {
            const uint32_t* b2h = &bh[nt >> 1][(nt & 1) * 2];
            const uint32_t* b2l = &bl[nt >> 1][(nt & 1) * 2];
            mma16816(acc[nt], ah, b2h);
            mma16816(acc[nt], ah, b2l);
            mma16816(acc[nt], al, b2h);
        }
    }

    int rb = m0 + wm + (lane >> 2);
    int cb = n0 + wn + (lane & 3) * 2;
    #pragma unroll
    for (int nt = 0; nt < 4; nt++) {
        int cc = cb + nt * 8;
        *reinterpret_cast<float2*>(&S[(size_t)rb * HID + cc]) =
            make_float2(acc[nt][0], acc[nt][1]);
        *reinterpret_cast<float2*>(&S[(size_t)(rb + 8) * HID + cc]) =
            make_float2(acc[nt][2], acc[nt][3]);
    }
}
#define SMEM_K256 (4 * BM * (256 * 2 + 16))

// ---------------- fused layer: agg(S_in)+bias+relu+residual -> x -> HMMA -> S_out ----
// MODE 0: A = x.  MODE 1: feat=(features+x)*0.5, A=feat, write fb.
// MODE 2: feat=(fb+x)*0.5, A=feat, write fb.
// BM=64 rows/CTA, BN=192 (all cols), K=192. smem: A hi/lo 2x25600 + B hi/lo 2x76800 = 204800.
#define F_ASTR 400
#define F_ASLAB (64 * F_ASTR)           // 25600
#define F_BSLAB (192 * F_ASTR)          // 76800
#define F_SMEM (2 * F_ASLAB + 2 * F_BSLAB)  // 204800

template <int MODE>
__global__ void __launch_bounds__(256, 1)
fused_layer(const float* __restrict__ Sin,
            const float* __restrict__ bias,
            const float* __restrict__ resptr,   // features (stride 256) or fb (stride 192)
            float* __restrict__ fb,
            const __nv_bfloat16* __restrict__ Wh, const __nv_bfloat16* __restrict__ Wl,
            const int* __restrict__ nidx, const float* __restrict__ nval,
            const int* __restrict__ ncnt,
            float* __restrict__ Sout)
{
    extern __shared__ char smem[];
    uint32_t sb = smem_u32(smem);
    const uint32_t sAH = sb, sAL = sb + F_ASLAB;
    const uint32_t sBH = sb + 2 * F_ASLAB, sBL = sb + 2 * F_ASLAB + F_BSLAB;
    __nv_bfloat16* aHI = reinterpret_cast<__nv_bfloat16*>(smem);
    __nv_bfloat16* aLO = reinterpret_cast<__nv_bfloat16*>(smem + F_ASLAB);

    int tid = threadIdx.x;
    int m0 = blockIdx.x * 64;
    int w = tid >> 5, lane = tid & 31;

    // ---- issue W tile loads first (192 rows x 24 segs, hi+lo) ----
    for (int v = tid; v < 192 * 24; v += 256) {
        int row = v / 24, seg = v % 24;
        uint32_t so = row * F_ASTR + seg * 16;
        size_t g = (size_t)row * 192 + seg * 8;
        cp16(sBH + so, Wh + g);
        cp16(sBL + so, Wl + g);
    }
    cp_commit();

    // ---- phase A: aggregate my 8 rows (2-row interleaved, 4-unrolled) ----
    float biasv[6];
    #pragma unroll
    for (int j = 0; j < 6; j++) biasv[j] = bias[lane + 32 * j];

    int wr0 = w * 8;
    for (int rr = 0; rr < 8; rr += 2) {
        int g0 = m0 + wr0 + rr, g1 = g0 + 1;
        int c0 = ncnt[g0], c1 = ncnt[g1];
        const int*   n0 = nidx + (size_t)g0 * MAXN;
        const int*   n1 = nidx + (size_t)g1 * MAXN;
        const float* v0 = nval + (size_t)g0 * MAXN;
        const float* v1 = nval + (size_t)g1 * MAXN;
        float p0 = 0.f, q0 = 0.f, p0b = 0.f, q0b = 0.f;
        float p1 = 0.f, q1 = 0.f, p1b = 0.f, q1b = 0.f;
        int mx = c0 > c1 ? c0 : c1;
        for (int i = 0; i < mx; i += 4) {
            if (i < c0) {
                int4   ji = *reinterpret_cast<const int4*>(n0 + i);
                float4 ui = *reinterpret_cast<const float4*>(v0 + i);
                const float* s0 = Sin + (size_t)ji.x * HID;
                const float* s1 = Sin + (size_t)ji.y * HID;
                const float* s2 = Sin + (size_t)ji.z * HID;
                const float* s3 = Sin + (size_t)ji.w * HID;
                p0  = fmaf(ui.x, s0[lane], p0);   q0  = fmaf(ui.x, s0[lane + 32], q0);
                p0b = fmaf(ui.y, s1[lane], p0b);  q0b = fmaf(ui.y, s1[lane + 32], q0b);
                p0  = fmaf(ui.z, s2[lane], p0);   q0  = fmaf(ui.z, s2[lane + 32], q0);
                p0b = fmaf(ui.w, s3[lane], p0b);  q0b = fmaf(ui.w, s3[lane + 32], q0b);
            }
            if (i < c1) {
                int4   ji = *reinterpret_cast<const int4*>(n1 + i);
                float4 ui = *reinterpret_cast<const float4*>(v1 + i);
                const float* s0 = Sin + (size_t)ji.x * HID;
                const float* s1 = Sin + (size_t)ji.y * HID;
                const float* s2 = Sin + (size_t)ji.z * HID;
                const float* s3 = Sin + (size_t)ji.w * HID;
                p1  = fmaf(ui.x, s0[lane], p1);   q1  = fmaf(ui.x, s0[lane + 32], q1);
                p1b = fmaf(ui.y, s1[lane], p1b);  q1b = fmaf(ui.y, s1[lane + 32], q1b);
                p1  = fmaf(ui.z, s2[lane], p1);   q1  = fmaf(ui.z, s2[lane + 32], q1);
                p1b = fmaf(ui.w, s3[lane], p1b);  q1b = fmaf(ui.w, s3[lane + 32], q1b);
            }
        }
        p0 += p0b; q0 += q0b; p1 += p1b; q1 += q1b;

        #pragma unroll
        for (int half = 0; half < 2; half++) {
            int g = half ? g1 : g0;
            int lr = wr0 + rr + half;
            float pa = half ? p1 : p0;
            float qa = half ? q1 : q0;
            #pragma unroll
            for (int j = 0; j < 6; j++) {
                int c = lane + 32 * j;
                float t = (j == 0) ? pa : (j == 1) ? qa : Sin[(size_t)g * HID + c];
                t += biasv[j];
                t = fmaxf(t, 0.f);
                if (MODE == 1) t = (resptr[(size_t)g * INF + c] + t) * 0.5f;
                if (MODE == 2) t = (resptr[(size_t)g * HID + c] + t) * 0.5f;
                if (MODE >= 1) fb[(size_t)g * HID + c] = t;
                __nv_bfloat16 h = __float2bfloat16(t);
                int so = lr * (F_ASTR / 2) + c;   // element index (2B units)
                aHI[so] = h;
                aLO[so] = __float2bfloat16(t - __bfloat162float(h));
            }
        }
    }

    cp_wait_all();
    __syncthreads();

    // ---- phase B: HMMA. warps 4m x 2n; warp tile 16 x 96 ----
    int wm = (w & 3) * 16;
    int wn = (w >> 2) * 96;
    float acc[12][4];
    #pragma unroll
    for (int nt = 0; nt < 12; nt++)
        #pragma unroll
        for (int q = 0; q < 4; q++) acc[nt][q] = 0.f;

    uint32_t aoff = (wm + (lane & 15)) * F_ASTR + (lane >> 4) * 16;
    uint32_t bbase = (wn + (lane & 7) + ((lane >> 4) << 3)) * F_ASTR + (((lane >> 3) & 1) * 16);

    #pragma unroll 2
    for (int ks = 0; ks < 12; ks++) {
        uint32_t ko = ks * 32;
        uint32_t ah[4], al[4], bh[6][4], bl[6][4];
        ldmx4(ah, sAH + aoff + ko);
        ldmx4(al, sAL + aoff + ko);
        #pragma unroll
        for (int p = 0; p < 6; p++) {
            uint32_t bo = bbase + p * 16 * F_ASTR + ko;
            ldmx4(bh[p], sBH + bo);
            ldmx4(bl[p], sBL + bo);
        }
        #pragma unroll
        for (int nt = 0; nt < 12; nt++) {
            const uint32_t* b2h = &bh[nt >> 1][(nt & 1) * 2];
            const uint32_t* b2l = &bl[nt >> 1][(nt & 1) * 2];
            mma16816(acc[nt], ah, b2h);
            mma16816(acc[nt], ah, b2l);
            mma16816(acc[nt], al, b2h);
        }
    }

    int rb = m0 + wm + (lane >> 2);
    int cb = wn + (lane & 3) * 2;
    #pragma unroll
    for (int nt = 0; nt < 12; nt++) {
        int cc = cb + nt * 8;
        *reinterpret_cast<float2*>(&Sout[(size_t)rb * HID + cc]) =
            make_float2(acc[nt][0], acc[nt][1]);
        *reinterpret_cast<float2*>(&Sout[(size_t)(rb + 8) * HID + cc]) =
            make_float2(acc[nt][2], acc[nt][3]);
    }
}

// ---------------- tiny GEMM for W_out (192x3) ----------------
__global__ __launch_bounds__(256) void gemm3_kernel(const float* __restrict__ X,
                                                    const float* __restrict__ W,
                                                    float* __restrict__ S)
{
    int r = blockIdx.x * blockDim.x + threadIdx.x;
    if (r >= NN) return;
    const float* x = X + (size_t)r * HID;
    float a0 = 0.f, a1 = 0.f, a2 = 0.f;
    #pragma unroll 4
    for (int k = 0; k < HID; k++) {
        float xv = x[k];
        a0 = fmaf(xv, W[k * 3 + 0], a0);
        a1 = fmaf(xv, W[k * 3 + 1], a1);
        a2 = fmaf(xv, W[k * 3 + 2], a2);
    }
    S[r * 3 + 0] = a0; S[r * 3 + 1] = a1; S[r * 3 + 2] = a2;
}

// ---------------- standalone aggregation (tail layers) ----------------
__global__ __launch_bounds__(256) void agg_kernel(const float* __restrict__ S,
                                                  const float* __restrict__ bias,
                                                  const float* __restrict__ res, int res_stride,
                                                  float* __restrict__ out,
                                                  float* __restrict__ out2,
                                                  const int* __restrict__ nidx,
                                                  const float* __restrict__ nval,
                                                  const int* __restrict__ ncnt,
                                                  int n_out, int side, int do_relu)
{
    int warp = (blockIdx.x * blockDim.x + threadIdx.x) >> 5;
    int lane = threadIdx.x & 31;
    if (warp >= NN) return;
    int cnt = ncnt[warp];
    const int* ni = nidx + (size_t)warp * MAXN;
    const float* nv = nval + (size_t)warp * MAXN;
    float acc0 = 0.f, acc1 = 0.f;
    if (side > 32) {
        float e0 = 0.f, e1 = 0.f;
        for (int i = 0; i < cnt; i += 4) {
            int4   ji = *reinterpret_cast<const int4*>(ni + i);
            float4 ui = *reinterpret_cast<const float4*>(nv + i);
            const float* s0 = S + (size_t)ji.x * n_out;
            const float* s1 = S + (size_t)ji.y * n_out;
            const float* s2 = S + (size_t)ji.z * n_out;
            const float* s3 = S + (size_t)ji.w * n_out;
            acc0 = fmaf(ui.x, s0[lane], acc0);  acc1 = fmaf(ui.x, s0[lane + 32], acc1);
            e0   = fmaf(ui.y, s1[lane], e0);    e1   = fmaf(ui.y, s1[lane + 32], e1);
            acc0 = fmaf(ui.z, s2[lane], acc0);  acc1 = fmaf(ui.z, s2[lane + 32], acc1);
            e0   = fmaf(ui.w, s3[lane], e0);    e1   = fmaf(ui.w, s3[lane + 32], e1);
        }
        acc0 += e0; acc1 += e1;
    } else {
        for (int i = 0; i < cnt; i++) {
            if (lane < side) acc0 = fmaf(nv[i], S[(size_t)ni[i] * n_out + lane], acc0);
        }
    }
    int nj = (n_out + 31) >> 5;
    for (int j = 0; j < nj; j++) {
        int c = 32 * j + lane;
        if (c < n_out) {
            float t = (c < side) ? (j == 0 ? acc0 : acc1)
                                 : S[(size_t)warp * n_out + c];
            t += bias[c];
            if (do_relu) t = fmaxf(t, 0.f);
            if (res) t = (res[(size_t)warp * res_stride + c] + t) * 0.5f;
            size_t idx = (size_t)warp * n_out + c;
            out[idx] = t;
            if (out2) out2[idx] = t;
        }
    }
}

extern "C" void kernel_launch(void* const* d_in, const int* in_sizes, int n_in,
                              void* d_out, int out_size)
{
    const float* features = (const float*)d_in[0];
    const float* adj      = (const float*)d_in[1];
    const float* W1       = (const float*)d_in[2];
    const float* b1       = (const float*)d_in[3];
    const float* W_mid    = (const float*)d_in[4];
    const float* b_mid    = (const float*)d_in[5];
    const float* W_out    = (const float*)d_in[6];
    const float* b_out    = (const float*)d_in[7];
    float* out = (float*)d_out;
    float* coords   = out;
    float* feat_out = out + NN * 3;

    float *sa, *sbuf, *fb, *sup3, *nval;
    __nv_bfloat16 *xhi, *xlo, *whi, *wlo;
    int *nidx, *ncnt;
    cudaGetSymbolAddress((void**)&sa,   g_supA);
    cudaGetSymbolAddress((void**)&sbuf, g_supB);
    cudaGetSymbolAddress((void**)&fb,   g_featbuf);
    cudaGetSymbolAddress((void**)&sup3, g_sup3);
    cudaGetSymbolAddress((void**)&xhi,  g_xhi);
    cudaGetSymbolAddress((void**)&xlo,  g_xlo);
    cudaGetSymbolAddress((void**)&whi,  g_wthi);
    cudaGetSymbolAddress((void**)&wlo,  g_wtlo);
    cudaGetSymbolAddress((void**)&nidx, g_nidx);
    cudaGetSymbolAddress((void**)&nval, g_nval);
    cudaGetSymbolAddress((void**)&ncnt, g_ncnt);

    cudaFuncSetAttribute(gemm_os<256>, cudaFuncAttributeMaxDynamicSharedMemorySize, SMEM_K256);
    cudaFuncSetAttribute(fused_layer<0>, cudaFuncAttributeMaxDynamicSharedMemorySize, F_SMEM);
    cudaFuncSetAttribute(fused_layer<1>, cudaFuncAttributeMaxDynamicSharedMemorySize, F_SMEM);
    cudaFuncSetAttribute(fused_layer<2>, cudaFuncAttributeMaxDynamicSharedMemorySize, F_SMEM);

    convert_weights<<<(WT_TOTAL + 255) / 256, 256>>>(W1, W_mid, whi, wlo);
    convert_features<<<(NN * INF + 255) / 256, 256>>>(features, xhi, xlo);
    build_csr<<<NN / 8, 256>>>(adj, nidx, nval, ncnt);

    auto woff = [](int i) { return (size_t)192 * 256 + (size_t)i * 192 * 192; };

    // gc1 gemm: S1 = features @ W1  -> sa
    dim3 g1(NN / BM, HID / BN);
    gemm_os<256><<<g1, 256, SMEM_K256>>>(xhi, xlo, whi, wlo, sa);

    // F2: agg gc1 (b1, no res) -> gemm Wmid0 -> sbuf
    fused_layer<0><<<NN / 64, 256, F_SMEM>>>(sa, b1, nullptr, fb,
        whi + woff(0), wlo + woff(0), nidx, nval, ncnt, sbuf);
    // F3: agg gc2 (bmid0, res=features) -> gemm Wmid1 -> sa
    fused_layer<1><<<NN / 64, 256, F_SMEM>>>(sbuf, b_mid + 0, features, fb,
        whi + woff(1), wlo + woff(1), nidx, nval, ncnt, sa);

    // F4..F13: aggs of gc3..gc12, gemms Wmid2..Wmid11
    float* cur = sa; float* nxt = sbuf;
    for (int p = 0; p < 5; p++) {
        int bi = 1 + 2 * p;       // agg bias index for first of pair (b_mid[bi])
        // first of pair: no residual; gemm W_mid[bi+1]
        fused_layer<0><<<NN / 64, 256, F_SMEM>>>(cur, b_mid + (size_t)bi * HID, nullptr, fb,
            whi + woff(bi + 1), wlo + woff(bi + 1), nidx, nval, ncnt, nxt);
        { float* t = cur; cur = nxt; nxt = t; }
        // second of pair: residual vs fb; gemm W_mid[bi+2]
        fused_layer<2><<<NN / 64, 256, F_SMEM>>>(cur, b_mid + (size_t)(bi + 1) * HID, fb, fb,
            whi + woff(bi + 2), wlo + woff(bi + 2), nidx, nval, ncnt, nxt);
        { float* t = cur; cur = nxt; nxt = t; }
    }
    // cur now holds S_gc13 (support of layer using Wmid11)

    // tail: agg gc13 (b_mid11, res=fb) -> fb (+ feat_out)
    agg_kernel<<<NN / 8, 256>>>(cur, b_mid + (size_t)11 * HID, fb, HID, fb, feat_out,
                                nidx, nval, ncnt, HID, 64, 1);
    // gc14: sup3 = feat @ W_out; coords = agg(side=2) + b_out
    gemm3_kernel<<<NN / 256, 256>>>(fb, W_out, sup3);
    agg_kernel<<<NN / 8, 256>>>(sup3, b_out, nullptr, 0, coords, nullptr,
                                nidx, nval, ncnt, 3, 2, 0);
}

// round 7
// speedup vs baseline: 1.5851x; 1.5851x over previous
#include <cuda_runtime.h>
#include <cuda_bf16.h>
#include <cstdint>
#include <cstddef>

#define NN   8192
#define HID  192
#define INF  256
#define MAXN 128

// ---------------- device scratch ----------------
__device__ float g_supA[NN * HID];
__device__ float g_supB[NN * HID];
__device__ float g_featbuf[NN * HID];
__device__ float g_sup3[NN * 3];
__device__ __nv_bfloat16 g_xhi[NN * INF];
__device__ __nv_bfloat16 g_xlo[NN * INF];
#define WT_TOTAL (192*256 + 12*192*192)
__device__ __nv_bfloat16 g_wthi[WT_TOTAL];
__device__ __nv_bfloat16 g_wtlo[WT_TOTAL];
__device__ int   g_nidx[NN * MAXN];
__device__ float g_nval[NN * MAXN];
__device__ int   g_ncnt[NN];

// ---------------- PTX helpers (compute_103-safe) ----------------
__device__ __forceinline__ uint32_t smem_u32(const void* p) {
    uint32_t a;
    asm("{ .reg .u64 t; cvta.to.shared.u64 t, %1; cvt.u32.u64 %0, t; }" : "=r"(a) : "l"(p));
    return a;
}
__device__ __forceinline__ void cp16(uint32_t d, const void* s) {
    asm volatile("cp.async.cg.shared.global [%0], [%1], 16;" :: "r"(d), "l"(s));
}
__device__ __forceinline__ void cp_commit() {
    asm volatile("cp.async.commit_group;" ::: "memory");
}
__device__ __forceinline__ void cp_wait_all() {
    asm volatile("cp.async.wait_all;" ::: "memory");
}
__device__ __forceinline__ void ldmx4(uint32_t* r, uint32_t a) {
    asm volatile("ldmatrix.sync.aligned.m8n8.x4.shared.b16 {%0,%1,%2,%3}, [%4];"
        : "=r"(r[0]), "=r"(r[1]), "=r"(r[2]), "=r"(r[3]) : "r"(a));
}
__device__ __forceinline__ void mma16816(float* d, const uint32_t* a, const uint32_t* b) {
    asm volatile("mma.sync.aligned.m16n8k16.row.col.f32.bf16.bf16.f32 "
        "{%0,%1,%2,%3}, {%4,%5,%6,%7}, {%8,%9}, {%0,%1,%2,%3};"
        : "+f"(d[0]), "+f"(d[1]), "+f"(d[2]), "+f"(d[3])
        : "r"(a[0]), "r"(a[1]), "r"(a[2]), "r"(a[3]), "r"(b[0]), "r"(b[1]));
}

// ---------------- CSR extraction (pads each row to multiple of 4) ----------------
__global__ __launch_bounds__(256) void build_csr(const float* __restrict__ adj,
                                                 int* __restrict__ nidx,
                                                 float* __restrict__ nval,
                                                 int* __restrict__ ncnt)
{
    int warp = (blockIdx.x * blockDim.x + threadIdx.x) >> 5;
    int lane = threadIdx.x & 31;
    if (warp >= NN) return;
    const float4* row = reinterpret_cast<const float4*>(adj + (size_t)warp * NN);
    int* my_idx = nidx + (size_t)warp * MAXN;
    float* my_val = nval + (size_t)warp * MAXN;
    int count = 0;
    for (int it = 0; it < NN / 128; it++) {
        float4 v = row[it * 32 + lane];
        int c0 = it * 128 + lane * 4;
        int my = (v.x != 0.f) + (v.y != 0.f) + (v.z != 0.f) + (v.w != 0.f);
        int inc = my;
        #pragma unroll
        for (int d = 1; d < 32; d <<= 1) {
            int t = __shfl_up_sync(0xffffffffu, inc, d);
            if (lane >= d) inc += t;
        }
        int total = __shfl_sync(0xffffffffu, inc, 31);
        int pos = count + inc - my;
        if (v.x != 0.f) { if (pos < MAXN) { my_idx[pos] = c0;     my_val[pos] = v.x; } pos++; }
        if (v.y != 0.f) { if (pos < MAXN) { my_idx[pos] = c0 + 1; my_val[pos] = v.y; } pos++; }
        if (v.z != 0.f) { if (pos < MAXN) { my_idx[pos] = c0 + 2; my_val[pos] = v.z; } pos++; }
        if (v.w != 0.f) { if (pos < MAXN) { my_idx[pos] = c0 + 3; my_val[pos] = v.w; } pos++; }
        count += total;
    }
    if (count > MAXN) count = MAXN;
    int padded = (count + 3) & ~3;
    if (padded > MAXN) padded = MAXN;
    for (int s = count + lane; s < padded; s += 32) { my_idx[s] = 0; my_val[s] = 0.f; }
    if (lane == 0) ncnt[warp] = padded;
}

// ---------------- weight / feature conversion ----------------
__global__ __launch_bounds__(256) void convert_weights(const float* __restrict__ W1,
                                                       const float* __restrict__ W_mid,
                                                       __nv_bfloat16* __restrict__ whi,
                                                       __nv_bfloat16* __restrict__ wlo)
{
    int idx = blockIdx.x * blockDim.x + threadIdx.x;
    if (idx >= WT_TOTAL) return;
    float w;
    if (idx < 192 * 256) {
        int n = idx / 256, k = idx % 256;
        w = W1[k * 192 + n];
    } else {
        int rel = idx - 192 * 256;
        int i = rel / (192 * 192);
        int r = rel % (192 * 192);
        int n = r / 192, k = r % 192;
        w = W_mid[(size_t)i * 192 * 192 + k * 192 + n];
    }
    __nv_bfloat16 h = __float2bfloat16(w);
    whi[idx] = h;
    wlo[idx] = __float2bfloat16(w - __bfloat162float(h));
}

__global__ __launch_bounds__(256) void convert_features(const float* __restrict__ f,
                                                        __nv_bfloat16* __restrict__ xhi,
                                                        __nv_bfloat16* __restrict__ xlo)
{
    int idx = blockIdx.x * blockDim.x + threadIdx.x;
    if (idx >= NN * INF) return;
    float v = f[idx];
    __nv_bfloat16 h = __float2bfloat16(v);
    xhi[idx] = h;
    xlo[idx] = __float2bfloat16(v - __bfloat162float(h));
}

// ---------------- gc1: one-shot split-bf16 HMMA GEMM, K=256, BN=64 ----------------
#define BM 64
#define BN 64
template <int KK>
__global__ void __launch_bounds__(256, 1)
gemm_os(const __nv_bfloat16* __restrict__ Xh, const __nv_bfloat16* __restrict__ Xl,
        const __nv_bfloat16* __restrict__ Wh, const __nv_bfloat16* __restrict__ Wl,
        float* __restrict__ S)
{
    constexpr int ASTR = KK * 2 + 16;
    constexpr int SLAB = BM * ASTR;
    constexpr int SEGS = KK / 8;
    extern __shared__ char smem[];
    uint32_t sb = smem_u32(smem);
    const uint32_t sAH = sb, sAL = sb + SLAB, sBH = sb + 2 * SLAB, sBL = sb + 3 * SLAB;

    int tid = threadIdx.x;
    int m0 = blockIdx.x * BM;
    int n0 = blockIdx.y * BN;
    int w = tid >> 5, lane = tid & 31;
    int wm = (w & 3) * 16;
    int wn = (w >> 2) * 32;

    #pragma unroll
    for (int v = tid; v < BM * SEGS; v += 256) {
        int row = v / SEGS, seg = v % SEGS;
        uint32_t so = row * ASTR + seg * 16;
        size_t ga = (size_t)(m0 + row) * KK + seg * 8;
        size_t gb = (size_t)(n0 + row) * KK + seg * 8;
        cp16(sAH + so, Xh + ga);
        cp16(sAL + so, Xl + ga);
        cp16(sBH + so, Wh + gb);
        cp16(sBL + so, Wl + gb);
    }
    cp_commit();

    float acc[4][4];
    #pragma unroll
    for (int nt = 0; nt < 4; nt++)
        #pragma unroll
        for (int q = 0; q < 4; q++) acc[nt][q] = 0.f;

    cp_wait_all();
    __syncthreads();

    uint32_t aoff = (wm + (lane & 15)) * ASTR + (lane >> 4) * 16;
    uint32_t boff0 = (wn + (lane & 7) + ((lane >> 4) << 3)) * ASTR + (((lane >> 3) & 1) * 16);
    uint32_t boff1 = boff0 + 16 * ASTR;

    #pragma unroll
    for (int ks = 0; ks < KK / 16; ks++) {
        uint32_t ko = ks * 32;
        uint32_t ah[4], al[4], bh[2][4], bl[2][4];
        ldmx4(ah, sAH + aoff + ko);
        ldmx4(al, sAL + aoff + ko);
        ldmx4(bh[0], sBH + boff0 + ko);
        ldmx4(bl[0], sBL + boff0 + ko);
        ldmx4(bh[1], sBH + boff1 + ko);
        ldmx4(bl[1], sBL + boff1 + ko);
        #pragma unroll
        for (int nt = 0; nt < 4; nt++) {
            const uint32_t* b2h = &bh[nt >> 1][(nt & 1) * 2];
            const uint32_t* b2l = &bl[nt >> 1][(nt & 1) * 2];
            mma16816(acc[nt], ah, b2h);
            mma16816(acc[nt], ah, b2l);
            mma16816(acc[nt], al, b2h);
        }
    }

    int rb = m0 + wm + (lane >> 2);
    int cb = n0 + wn + (lane & 3) * 2;
    #pragma unroll
    for (int nt = 0; nt < 4; nt++) {
        int cc = cb + nt * 8;
        *reinterpret_cast<float2*>(&S[(size_t)rb * HID + cc]) =
            make_float2(acc[nt][0], acc[nt][1]);
        *reinterpret_cast<float2*>(&S[(size_t)(rb + 8) * HID + cc]) =
            make_float2(acc[nt][2], acc[nt][3]);
    }
}
#define SMEM_K256 (4 * BM * (256 * 2 + 16))

// ---------------- mid-layer GEMM: BM=64, BN=192 (full), K=192, 512 thr ----------------
// One-shot load; A read once per layer. 16 warps = 4m x 4n, warp tile 16x48.
#define GF_ASTR 400
#define GF_ASLAB (64 * GF_ASTR)            // 25600
#define GF_BSLAB (192 * GF_ASTR)           // 76800
#define GF_SMEM (2 * GF_ASLAB + 2 * GF_BSLAB)  // 204800

__global__ void __launch_bounds__(512, 1)
gemm_full(const __nv_bfloat16* __restrict__ Xh, const __nv_bfloat16* __restrict__ Xl,
          const __nv_bfloat16* __restrict__ Wh, const __nv_bfloat16* __restrict__ Wl,
          float* __restrict__ S)
{
    extern __shared__ char smem[];
    uint32_t sb = smem_u32(smem);
    const uint32_t sAH = sb, sAL = sb + GF_ASLAB;
    const uint32_t sBH = sb + 2 * GF_ASLAB, sBL = sb + 2 * GF_ASLAB + GF_BSLAB;

    int tid = threadIdx.x;
    int m0 = blockIdx.x * 64;
    int w = tid >> 5, lane = tid & 31;
    int wm = (w & 3) * 16;
    int wn = (w >> 2) * 48;

    // A: 64 rows x 24 segs; B: 192 rows x 24 segs (hi+lo)
    #pragma unroll
    for (int v = tid; v < 64 * 24; v += 512) {
        int row = v / 24, seg = v % 24;
        uint32_t so = row * GF_ASTR + seg * 16;
        size_t g = (size_t)(m0 + row) * 192 + seg * 8;
        cp16(sAH + so, Xh + g);
        cp16(sAL + so, Xl + g);
    }
    #pragma unroll
    for (int v = tid; v < 192 * 24; v += 512) {
        int row = v / 24, seg = v % 24;
        uint32_t so = row * GF_ASTR + seg * 16;
        size_t g = (size_t)row * 192 + seg * 8;
        cp16(sBH + so, Wh + g);
        cp16(sBL + so, Wl + g);
    }
    cp_commit();

    float acc[6][4];
    #pragma unroll
    for (int nt = 0; nt < 6; nt++)
        #pragma unroll
        for (int q = 0; q < 4; q++) acc[nt][q] = 0.f;

    cp_wait_all();
    __syncthreads();

    uint32_t aoff = (wm + (lane & 15)) * GF_ASTR + (lane >> 4) * 16;
    uint32_t bbase = (wn + (lane & 7) + ((lane >> 4) << 3)) * GF_ASTR + (((lane >> 3) & 1) * 16);

    #pragma unroll
    for (int ks = 0; ks < 12; ks++) {
        uint32_t ko = ks * 32;
        uint32_t ah[4], al[4], bh[3][4], bl[3][4];
        ldmx4(ah, sAH + aoff + ko);
        ldmx4(al, sAL + aoff + ko);
        #pragma unroll
        for (int p = 0; p < 3; p++) {
            uint32_t bo = bbase + p * 16 * GF_ASTR + ko;
            ldmx4(bh[p], sBH + bo);
            ldmx4(bl[p], sBL + bo);
        }
        #pragma unroll
        for (int nt = 0; nt < 6; nt++) {
            const uint32_t* b2h = &bh[nt >> 1][(nt & 1) * 2];
            const uint32_t* b2l = &bl[nt >> 1][(nt & 1) * 2];
            mma16816(acc[nt], ah, b2h);
            mma16816(acc[nt], ah, b2l);
            mma16816(acc[nt], al, b2h);
        }
    }

    int rb = m0 + wm + (lane >> 2);
    int cb = wn + (lane & 3) * 2;
    #pragma unroll
    for (int nt = 0; nt < 6; nt++) {
        int cc = cb + nt * 8;
        *reinterpret_cast<float2*>(&S[(size_t)rb * HID + cc]) =
            make_float2(acc[nt][0], acc[nt][1]);
        *reinterpret_cast<float2*>(&S[(size_t)(rb + 8) * HID + cc]) =
            make_float2(acc[nt][2], acc[nt][3]);
    }
}

// ---------------- fast aggregation: float4 gathers, one warp per row ----------------
// MODE 0: no residual, no fp32 out (hi/lo only).
// MODE 1: res=features (stride 256), writes fbout fp32 + hi/lo.
// MODE 2: res=fb (stride 192), writes fbout fp32 + hi/lo.
template <int MODE>
__global__ __launch_bounds__(256) void agg2(const float* __restrict__ S,
                                            const float* __restrict__ bias,
                                            const float* __restrict__ resptr,
                                            float* __restrict__ fbout,
                                            __nv_bfloat16* __restrict__ ohi,
                                            __nv_bfloat16* __restrict__ olo,
                                            const int* __restrict__ nidx,
                                            const float* __restrict__ nval,
                                            const int* __restrict__ ncnt)
{
    int row = (blockIdx.x * blockDim.x + threadIdx.x) >> 5;
    int lane = threadIdx.x & 31;
    if (row >= NN) return;
    int half = lane >> 4, sl = lane & 15;
    int cnt = ncnt[row];
    const int* ni = nidx + (size_t)row * MAXN;
    const float* nv = nval + (size_t)row * MAXN;

    float a0 = 0.f, a1 = 0.f, a2 = 0.f, a3 = 0.f;
    float b0 = 0.f, b1 = 0.f, b2 = 0.f, b3 = 0.f;
    for (int i = 0; i < cnt; i += 4) {
        int4   ji = *reinterpret_cast<const int4*>(ni + i);
        float4 wv = *reinterpret_cast<const float4*>(nv + i);
        int   nA = half ? ji.y : ji.x;  float wA = half ? wv.y : wv.x;
        int   nB = half ? ji.w : ji.z;  float wB = half ? wv.w : wv.z;
        float4 vA = *reinterpret_cast<const float4*>(S + (size_t)nA * HID + 4 * sl);
        float4 vB = *reinterpret_cast<const float4*>(S + (size_t)nB * HID + 4 * sl);
        a0 = fmaf(wA, vA.x, a0); a1 = fmaf(wA, vA.y, a1);
        a2 = fmaf(wA, vA.z, a2); a3 = fmaf(wA, vA.w, a3);
        b0 = fmaf(wB, vB.x, b0); b1 = fmaf(wB, vB.y, b1);
        b2 = fmaf(wB, vB.z, b2); b3 = fmaf(wB, vB.w, b3);
    }
    a0 += b0; a1 += b1; a2 += b2; a3 += b3;
    a0 += __shfl_xor_sync(0xffffffffu, a0, 16);
    a1 += __shfl_xor_sync(0xffffffffu, a1, 16);
    a2 += __shfl_xor_sync(0xffffffffu, a2, 16);
    a3 += __shfl_xor_sync(0xffffffffu, a3, 16);

    size_t rbase = (size_t)row * HID;

    // side cols 0..63 (lanes 0..15, 4 cols each)
    if (lane < 16) {
        int c = 4 * sl;
        float4 bs = *reinterpret_cast<const float4*>(bias + c);
        float t0 = fmaxf(a0 + bs.x, 0.f);
        float t1 = fmaxf(a1 + bs.y, 0.f);
        float t2 = fmaxf(a2 + bs.z, 0.f);
        float t3 = fmaxf(a3 + bs.w, 0.f);
        if (MODE == 1) {
            float4 rv = *reinterpret_cast<const float4*>(resptr + (size_t)row * INF + c);
            t0 = (rv.x + t0) * 0.5f; t1 = (rv.y + t1) * 0.5f;
            t2 = (rv.z + t2) * 0.5f; t3 = (rv.w + t3) * 0.5f;
        }
        if (MODE == 2) {
            float4 rv = *reinterpret_cast<const float4*>(resptr + rbase + c);
            t0 = (rv.x + t0) * 0.5f; t1 = (rv.y + t1) * 0.5f;
            t2 = (rv.z + t2) * 0.5f; t3 = (rv.w + t3) * 0.5f;
        }
        if (MODE >= 1)
            *reinterpret_cast<float4*>(fbout + rbase + c) = make_float4(t0, t1, t2, t3);
        __nv_bfloat16 h0 = __float2bfloat16(t0), h1 = __float2bfloat16(t1);
        __nv_bfloat16 h2 = __float2bfloat16(t2), h3 = __float2bfloat16(t3);
        __nv_bfloat162 hp0; hp0.x = h0; hp0.y = h1;
        __nv_bfloat162 hp1; hp1.x = h2; hp1.y = h3;
        *reinterpret_cast<__nv_bfloat162*>(ohi + rbase + c)     = hp0;
        *reinterpret_cast<__nv_bfloat162*>(ohi + rbase + c + 2) = hp1;
        __nv_bfloat162 lp0, lp1;
        lp0.x = __float2bfloat16(t0 - __bfloat162float(h0));
        lp0.y = __float2bfloat16(t1 - __bfloat162float(h1));
        lp1.x = __float2bfloat16(t2 - __bfloat162float(h2));
        lp1.y = __float2bfloat16(t3 - __bfloat162float(h3));
        *reinterpret_cast<__nv_bfloat162*>(olo + rbase + c)     = lp0;
        *reinterpret_cast<__nv_bfloat162*>(olo + rbase + c + 2) = lp1;
    }

    // passthrough cols 64..191 (32 lanes x 4 cols)
    {
        int c = 64 + 4 * lane;
        float4 sv = *reinterpret_cast<const float4*>(S + rbase + c);
        float4 bs = *reinterpret_cast<const float4*>(bias + c);
        float t0 = fmaxf(sv.x + bs.x, 0.f);
        float t1 = fmaxf(sv.y + bs.y, 0.f);
        float t2 = fmaxf(sv.z + bs.z, 0.f);
        float t3 = fmaxf(sv.w + bs.w, 0.f);
        if (MODE == 1) {
            float4 rv = *reinterpret_cast<const float4*>(resptr + (size_t)row * INF + c);
            t0 = (rv.x + t0) * 0.5f; t1 = (rv.y + t1) * 0.5f;
            t2 = (rv.z + t2) * 0.5f; t3 = (rv.w + t3) * 0.5f;
        }
        if (MODE == 2) {
            float4 rv = *reinterpret_cast<const float4*>(resptr + rbase + c);
            t0 = (rv.x + t0) * 0.5f; t1 = (rv.y + t1) * 0.5f;
            t2 = (rv.z + t2) * 0.5f; t3 = (rv.w + t3) * 0.5f;
        }
        if (MODE >= 1)
            *reinterpret_cast<float4*>(fbout + rbase + c) = make_float4(t0, t1, t2, t3);
        __nv_bfloat16 h0 = __float2bfloat16(t0), h1 = __float2bfloat16(t1);
        __nv_bfloat16 h2 = __float2bfloat16(t2), h3 = __float2bfloat16(t3);
        __nv_bfloat162 hp0; hp0.x = h0; hp0.y = h1;
        __nv_bfloat162 hp1; hp1.x = h2; hp1.y = h3;
        *reinterpret_cast<__nv_bfloat162*>(ohi + rbase + c)     = hp0;
        *reinterpret_cast<__nv_bfloat162*>(ohi + rbase + c + 2) = hp1;
        __nv_bfloat162 lp0, lp1;
        lp0.x = __float2bfloat16(t0 - __bfloat162float(h0));
        lp0.y = __float2bfloat16(t1 - __bfloat162float(h1));
        lp1.x = __float2bfloat16(t2 - __bfloat162float(h2));
        lp1.y = __float2bfloat16(t3 - __bfloat162float(h3));
        *reinterpret_cast<__nv_bfloat162*>(olo + rbase + c)     = lp0;
        *reinterpret_cast<__nv_bfloat162*>(olo + rbase + c + 2) = lp1;
    }
}

// ---------------- tiny GEMM for W_out (192x3) ----------------
__global__ __launch_bounds__(256) void gemm3_kernel(const float* __restrict__ X,
                                                    const float* __restrict__ W,
                                                    float* __restrict__ S)
{
    int r = blockIdx.x * blockDim.x + threadIdx.x;
    if (r >= NN) return;
    const float* x = X + (size_t)r * HID;
    float a0 = 0.f, a1 = 0.f, a2 = 0.f;
    #pragma unroll 4
    for (int k = 0; k < HID; k++) {
        float xv = x[k];
        a0 = fmaf(xv, W[k * 3 + 0], a0);
        a1 = fmaf(xv, W[k * 3 + 1], a1);
        a2 = fmaf(xv, W[k * 3 + 2], a2);
    }
    S[r * 3 + 0] = a0; S[r * 3 + 1] = a1; S[r * 3 + 2] = a2;
}

// ---------------- standalone aggregation (tail layers, fp32 out) ----------------
__global__ __launch_bounds__(256) void agg_kernel(const float* __restrict__ S,
                                                  const float* __restrict__ bias,
                                                  const float* __restrict__ res, int res_stride,
                                                  float* __restrict__ out,
                                                  float* __restrict__ out2,
                                                  const int* __restrict__ nidx,
                                                  const float* __restrict__ nval,
                                                  const int* __restrict__ ncnt,
                                                  int n_out, int side, int do_relu)
{
    int warp = (blockIdx.x * blockDim.x + threadIdx.x) >> 5;
    int lane = threadIdx.x & 31;
    if (warp >= NN) return;
    int cnt = ncnt[warp];
    const int* ni = nidx + (size_t)warp * MAXN;
    const float* nv = nval + (size_t)warp * MAXN;
    float acc0 = 0.f, acc1 = 0.f;
    if (side > 32) {
        float e0 = 0.f, e1 = 0.f;
        for (int i = 0; i < cnt; i += 4) {
            int4   ji = *reinterpret_cast<const int4*>(ni + i);
            float4 ui = *reinterpret_cast<const float4*>(nv + i);
            const float* s0 = S + (size_t)ji.x * n_out;
            const float* s1 = S + (size_t)ji.y * n_out;
            const float* s2 = S + (size_t)ji.z * n_out;
            const float* s3 = S + (size_t)ji.w * n_out;
            acc0 = fmaf(ui.x, s0[lane], acc0);  acc1 = fmaf(ui.x, s0[lane + 32], acc1);
            e0   = fmaf(ui.y, s1[lane], e0);    e1   = fmaf(ui.y, s1[lane + 32], e1);
            acc0 = fmaf(ui.z, s2[lane], acc0);  acc1 = fmaf(ui.z, s2[lane + 32], acc1);
            e0   = fmaf(ui.w, s3[lane], e0);    e1   = fmaf(ui.w, s3[lane + 32], e1);
        }
        acc0 += e0; acc1 += e1;
    } else {
        for (int i = 0; i < cnt; i++) {
            if (lane < side) acc0 = fmaf(nv[i], S[(size_t)ni[i] * n_out + lane], acc0);
        }
    }
    int nj = (n_out + 31) >> 5;
    for (int j = 0; j < nj; j++) {
        int c = 32 * j + lane;
        if (c < n_out) {
            float t = (c < side) ? (j == 0 ? acc0 : acc1)
                                 : S[(size_t)warp * n_out + c];
            t += bias[c];
            if (do_relu) t = fmaxf(t, 0.f);
            if (res) t = (res[(size_t)warp * res_stride + c] + t) * 0.5f;
            size_t idx = (size_t)warp * n_out + c;
            out[idx] = t;
            if (out2) out2[idx] = t;
        }
    }
}

extern "C" void kernel_launch(void* const* d_in, const int* in_sizes, int n_in,
                              void* d_out, int out_size)
{
    const float* features = (const float*)d_in[0];
    const float* adj      = (const float*)d_in[1];
    const float* W1       = (const float*)d_in[2];
    const float* b1       = (const float*)d_in[3];
    const float* W_mid    = (const float*)d_in[4];
    const float* b_mid    = (const float*)d_in[5];
    const float* W_out    = (const float*)d_in[6];
    const float* b_out    = (const float*)d_in[7];
    float* out = (float*)d_out;
    float* coords   = out;
    float* feat_out = out + NN * 3;

    float *sa, *sbuf, *fb, *sup3, *nval;
    __nv_bfloat16 *xhi, *xlo, *whi, *wlo;
    int *nidx, *ncnt;
    cudaGetSymbolAddress((void**)&sa,   g_supA);
    cudaGetSymbolAddress((void**)&sbuf, g_supB);
    cudaGetSymbolAddress((void**)&fb,   g_featbuf);
    cudaGetSymbolAddress((void**)&sup3, g_sup3);
    cudaGetSymbolAddress((void**)&xhi,  g_xhi);
    cudaGetSymbolAddress((void**)&xlo,  g_xlo);
    cudaGetSymbolAddress((void**)&whi,  g_wthi);
    cudaGetSymbolAddress((void**)&wlo,  g_wtlo);
    cudaGetSymbolAddress((void**)&nidx, g_nidx);
    cudaGetSymbolAddress((void**)&nval, g_nval);
    cudaGetSymbolAddress((void**)&ncnt, g_ncnt);

    cudaFuncSetAttribute(gemm_os<256>, cudaFuncAttributeMaxDynamicSharedMemorySize, SMEM_K256);
    cudaFuncSetAttribute(gemm_full, cudaFuncAttributeMaxDynamicSharedMemorySize, GF_SMEM);

    // csr FIRST: its 268MB adj sweep evicts L2; converted tensors stay hot after.
    build_csr<<<NN / 8, 256>>>(adj, nidx, nval, ncnt);
    convert_weights<<<(WT_TOTAL + 255) / 256, 256>>>(W1, W_mid, whi, wlo);
    convert_features<<<(NN * INF + 255) / 256, 256>>>(features, xhi, xlo);

    auto woff = [](int i) { return (size_t)192 * 256 + (size_t)i * 192 * 192; };

    // gc1 gemm: S1 = features @ W1 -> sa
    dim3 g1(NN / BM, HID / BN);
    gemm_os<256><<<g1, 256, SMEM_K256>>>(xhi, xlo, whi, wlo, sa);

    // agg gc1 (b1) -> hi/lo ; gemm Wmid0 -> sbuf
    agg2<0><<<NN / 8, 256>>>(sa, b1, nullptr, nullptr, xhi, xlo, nidx, nval, ncnt);
    gemm_full<<<NN / 64, 512, GF_SMEM>>>(xhi, xlo, whi + woff(0), wlo + woff(0), sbuf);
    // agg gc2 (bmid0, res=features) -> fb + hi/lo ; gemm Wmid1 -> sa
    agg2<1><<<NN / 8, 256>>>(sbuf, b_mid + 0, features, fb, xhi, xlo, nidx, nval, ncnt);
    gemm_full<<<NN / 64, 512, GF_SMEM>>>(xhi, xlo, whi + woff(1), wlo + woff(1), sa);

    float* cur = sa; float* nxt = sbuf;
    for (int p = 0; p < 5; p++) {
        int bi = 1 + 2 * p;
        agg2<0><<<NN / 8, 256>>>(cur, b_mid + (size_t)bi * HID, nullptr, nullptr,
                                 xhi, xlo, nidx, nval, ncnt);
        gemm_full<<<NN / 64, 512, GF_SMEM>>>(xhi, xlo, whi + woff(bi + 1), wlo + woff(bi + 1), nxt);
        { float* t = cur; cur = nxt; nxt = t; }
        agg2<2><<<NN / 8, 256>>>(cur, b_mid + (size_t)(bi + 1) * HID, fb, fb,
                                 xhi, xlo, nidx, nval, ncnt);
        gemm_full<<<NN / 64, 512, GF_SMEM>>>(xhi, xlo, whi + woff(bi + 2), wlo + woff(bi + 2), nxt);
        { float* t = cur; cur = nxt; nxt = t; }
    }
    // cur holds S_gc13

    // tail: agg gc13 (b_mid11, res=fb) -> fb (+ feat_out)
    agg_kernel<<<NN / 8, 256>>>(cur, b_mid + (size_t)11 * HID, fb, HID, fb, feat_out,
                                nidx, nval, ncnt, HID, 64, 1);
    // gc14: sup3 = feat @ W_out; coords
    gemm3_kernel<<<NN / 256, 256>>>(fb, W_out, sup3);
    agg_kernel<<<NN / 8, 256>>>(sup3, b_out, nullptr, 0, coords, nullptr,
                                nidx, nval, ncnt, 3, 2, 0);
}

// round 8
// speedup vs baseline: 1.8058x; 1.1392x over previous
#include <cuda_runtime.h>
#include <cuda_bf16.h>
#include <cstdint>
#include <cstddef>

#define NN   8192
#define HID  192
#define INF  256
#define MAXN 128

// ---------------- device scratch ----------------
__device__ float g_supA[NN * HID];
__device__ float g_supB[NN * HID];
__device__ float g_featbuf[NN * HID];
__device__ float g_sup3[NN * 3];
__device__ __nv_bfloat16 g_xhi[NN * INF];
__device__ __nv_bfloat16 g_xlo[NN * INF];
#define WT_TOTAL (192*256 + 12*192*192)
__device__ __nv_bfloat16 g_wthi[WT_TOTAL];
__device__ __nv_bfloat16 g_wtlo[WT_TOTAL];
__device__ int   g_nidx[NN * MAXN];
__device__ float g_nval[NN * MAXN];
__device__ int   g_ncnt[NN];

// ---------------- PTX helpers (compute_103-safe) ----------------
__device__ __forceinline__ uint32_t smem_u32(const void* p) {
    uint32_t a;
    asm("{ .reg .u64 t; cvta.to.shared.u64 t, %1; cvt.u32.u64 %0, t; }" : "=r"(a) : "l"(p));
    return a;
}
__device__ __forceinline__ void cp16(uint32_t d, const void* s) {
    asm volatile("cp.async.cg.shared.global [%0], [%1], 16;" :: "r"(d), "l"(s));
}
__device__ __forceinline__ void cp_commit() {
    asm volatile("cp.async.commit_group;" ::: "memory");
}
template <int N> __device__ __forceinline__ void cp_wait() {
    asm volatile("cp.async.wait_group %0;" :: "n"(N) : "memory");
}
__device__ __forceinline__ void ldmx4(uint32_t* r, uint32_t a) {
    asm volatile("ldmatrix.sync.aligned.m8n8.x4.shared.b16 {%0,%1,%2,%3}, [%4];"
        : "=r"(r[0]), "=r"(r[1]), "=r"(r[2]), "=r"(r[3]) : "r"(a));
}
__device__ __forceinline__ void mma16816(float* d, const uint32_t* a, const uint32_t* b) {
    asm volatile("mma.sync.aligned.m16n8k16.row.col.f32.bf16.bf16.f32 "
        "{%0,%1,%2,%3}, {%4,%5,%6,%7}, {%8,%9}, {%0,%1,%2,%3};"
        : "+f"(d[0]), "+f"(d[1]), "+f"(d[2]), "+f"(d[3])
        : "r"(a[0]), "r"(a[1]), "r"(a[2]), "r"(a[3]), "r"(b[0]), "r"(b[1]));
}

// ---------------- CSR extraction (pads each row to multiple of 4) ----------------
__global__ __launch_bounds__(256) void build_csr(const float* __restrict__ adj,
                                                 int* __restrict__ nidx,
                                                 float* __restrict__ nval,
                                                 int* __restrict__ ncnt)
{
    int warp = (blockIdx.x * blockDim.x + threadIdx.x) >> 5;
    int lane = threadIdx.x & 31;
    if (warp >= NN) return;
    const float4* row = reinterpret_cast<const float4*>(adj + (size_t)warp * NN);
    int* my_idx = nidx + (size_t)warp * MAXN;
    float* my_val = nval + (size_t)warp * MAXN;
    int count = 0;
    for (int it = 0; it < NN / 128; it++) {
        float4 v = row[it * 32 + lane];
        int c0 = it * 128 + lane * 4;
        int my = (v.x != 0.f) + (v.y != 0.f) + (v.z != 0.f) + (v.w != 0.f);
        int inc = my;
        #pragma unroll
        for (int d = 1; d < 32; d <<= 1) {
            int t = __shfl_up_sync(0xffffffffu, inc, d);
            if (lane >= d) inc += t;
        }
        int total = __shfl_sync(0xffffffffu, inc, 31);
        int pos = count + inc - my;
        if (v.x != 0.f) { if (pos < MAXN) { my_idx[pos] = c0;     my_val[pos] = v.x; } pos++; }
        if (v.y != 0.f) { if (pos < MAXN) { my_idx[pos] = c0 + 1; my_val[pos] = v.y; } pos++; }
        if (v.z != 0.f) { if (pos < MAXN) { my_idx[pos] = c0 + 2; my_val[pos] = v.z; } pos++; }
        if (v.w != 0.f) { if (pos < MAXN) { my_idx[pos] = c0 + 3; my_val[pos] = v.w; } pos++; }
        count += total;
    }
    if (count > MAXN) count = MAXN;
    int padded = (count + 3) & ~3;
    if (padded > MAXN) padded = MAXN;
    for (int s = count + lane; s < padded; s += 32) { my_idx[s] = 0; my_val[s] = 0.f; }
    if (lane == 0) ncnt[warp] = padded;
}

// ---------------- weight / feature conversion ----------------
__global__ __launch_bounds__(256) void convert_weights(const float* __restrict__ W1,
                                                       const float* __restrict__ W_mid,
                                                       __nv_bfloat16* __restrict__ whi,
                                                       __nv_bfloat16* __restrict__ wlo)
{
    int idx = blockIdx.x * blockDim.x + threadIdx.x;
    if (idx >= WT_TOTAL) return;
    float w;
    if (idx < 192 * 256) {
        int n = idx / 256, k = idx % 256;
        w = W1[k * 192 + n];
    } else {
        int rel = idx - 192 * 256;
        int i = rel / (192 * 192);
        int r = rel % (192 * 192);
        int n = r / 192, k = r % 192;
        w = W_mid[(size_t)i * 192 * 192 + k * 192 + n];
    }
    __nv_bfloat16 h = __float2bfloat16(w);
    whi[idx] = h;
    wlo[idx] = __float2bfloat16(w - __bfloat162float(h));
}

__global__ __launch_bounds__(256) void convert_features(const float* __restrict__ f,
                                                        __nv_bfloat16* __restrict__ xhi,
                                                        __nv_bfloat16* __restrict__ xlo)
{
    int idx = blockIdx.x * blockDim.x + threadIdx.x;
    if (idx >= NN * INF) return;
    float v = f[idx];
    __nv_bfloat16 h = __float2bfloat16(v);
    xhi[idx] = h;
    xlo[idx] = __float2bfloat16(v - __bfloat162float(h));
}

// ---------------- gc1: 2-chunk pipelined split-bf16 HMMA, K=256, BM=BN=64 ----------------
#define BM 64
#define BN 64
__global__ void __launch_bounds__(256, 1)
gemm_os(const __nv_bfloat16* __restrict__ Xh, const __nv_bfloat16* __restrict__ Xl,
        const __nv_bfloat16* __restrict__ Wh, const __nv_bfloat16* __restrict__ Wl,
        float* __restrict__ S)
{
    constexpr int KK = 256;
    constexpr int ASTR = KK * 2 + 16;
    constexpr int SLAB = BM * ASTR;
    extern __shared__ char smem[];
    uint32_t sb = smem_u32(smem);
    const uint32_t sAH = sb, sAL = sb + SLAB, sBH = sb + 2 * SLAB, sBL = sb + 3 * SLAB;

    int tid = threadIdx.x;
    int m0 = blockIdx.x * BM;
    int n0 = blockIdx.y * BN;
    int w = tid >> 5, lane = tid & 31;
    int wm = (w & 3) * 16;
    int wn = (w >> 2) * 32;

    auto load_chunk = [&](int ch) {   // 128 cols = 16 segs per row
        #pragma unroll
        for (int v = tid; v < BM * 16; v += 256) {
            int row = v >> 4, seg = v & 15;
            uint32_t so = row * ASTR + (ch * 16 + seg) * 16;
            size_t ga = (size_t)(m0 + row) * KK + ch * 128 + seg * 8;
            size_t gb = (size_t)(n0 + row) * KK + ch * 128 + seg * 8;
            cp16(sAH + so, Xh + ga);
            cp16(sAL + so, Xl + ga);
            cp16(sBH + so, Wh + gb);
            cp16(sBL + so, Wl + gb);
        }
    };
    load_chunk(0); cp_commit();
    load_chunk(1); cp_commit();

    float acc[4][4];
    #pragma unroll
    for (int nt = 0; nt < 4; nt++)
        #pragma unroll
        for (int q = 0; q < 4; q++) acc[nt][q] = 0.f;

    uint32_t aoff = (wm + (lane & 15)) * ASTR + (lane >> 4) * 16;
    uint32_t boff0 = (wn + (lane & 7) + ((lane >> 4) << 3)) * ASTR + (((lane >> 3) & 1) * 16);
    uint32_t boff1 = boff0 + 16 * ASTR;

    auto compute_range = [&](int k0, int k1) {
        #pragma unroll
        for (int ks = k0; ks < k1; ks++) {
            uint32_t ko = ks * 32;
            uint32_t ah[4], al[4], bh[2][4], bl[2][4];
            ldmx4(ah, sAH + aoff + ko);
            ldmx4(al, sAL + aoff + ko);
            ldmx4(bh[0], sBH + boff0 + ko);
            ldmx4(bl[0], sBL + boff0 + ko);
            ldmx4(bh[1], sBH + boff1 + ko);
            ldmx4(bl[1], sBL + boff1 + ko);
            #pragma unroll
            for (int nt = 0; nt < 4; nt++) {
                const uint32_t* b2h = &bh[nt >> 1][(nt & 1) * 2];
                const uint32_t* b2l = &bl[nt >> 1][(nt & 1) * 2];
                mma16816(acc[nt], ah, b2h);
                mma16816(acc[nt], ah, b2l);
                mma16816(acc[nt], al, b2h);
            }
        }
    };

    cp_wait<1>(); __syncthreads();
    compute_range(0, 8);
    cp_wait<0>(); __syncthreads();
    compute_range(8, 16);

    int rb = m0 + wm + (lane >> 2);
    int cb = n0 + wn + (lane & 3) * 2;
    #pragma unroll
    for (int nt = 0; nt < 4; nt++) {
        int cc = cb + nt * 8;
        *reinterpret_cast<float2*>(&S[(size_t)rb * HID + cc]) =
            make_float2(acc[nt][0], acc[nt][1]);
        *reinterpret_cast<float2*>(&S[(size_t)(rb + 8) * HID + cc]) =
            make_float2(acc[nt][2], acc[nt][3]);
    }
}
#define SMEM_K256 (4 * BM * (256 * 2 + 16))

// ---------------- mid-layer GEMM: BM=64, BN=192, K=192, 512 thr, 2-chunk pipeline ----
#define GF_ASTR 400
#define GF_ASLAB (64 * GF_ASTR)
#define GF_BSLAB (192 * GF_ASTR)
#define GF_SMEM (2 * GF_ASLAB + 2 * GF_BSLAB)   // 204800

__global__ void __launch_bounds__(512, 1)
gemm_full(const __nv_bfloat16* __restrict__ Xh, const __nv_bfloat16* __restrict__ Xl,
          const __nv_bfloat16* __restrict__ Wh, const __nv_bfloat16* __restrict__ Wl,
          float* __restrict__ S)
{
    extern __shared__ char smem[];
    uint32_t sb = smem_u32(smem);
    const uint32_t sAH = sb, sAL = sb + GF_ASLAB;
    const uint32_t sBH = sb + 2 * GF_ASLAB, sBL = sb + 2 * GF_ASLAB + GF_BSLAB;

    int tid = threadIdx.x;
    int m0 = blockIdx.x * 64;
    int w = tid >> 5, lane = tid & 31;
    int wm = (w & 3) * 16;
    int wn = (w >> 2) * 48;

    auto load_chunk = [&](int ch) {   // 96 cols = 12 segs per row
        #pragma unroll
        for (int v = tid; v < 64 * 12; v += 512) {
            int row = v / 12, seg = v % 12;
            uint32_t so = row * GF_ASTR + (ch * 12 + seg) * 16;
            size_t g = (size_t)(m0 + row) * 192 + ch * 96 + seg * 8;
            cp16(sAH + so, Xh + g);
            cp16(sAL + so, Xl + g);
        }
        #pragma unroll
        for (int v = tid; v < 192 * 12; v += 512) {
            int row = v / 12, seg = v % 12;
            uint32_t so = row * GF_ASTR + (ch * 12 + seg) * 16;
            size_t g = (size_t)row * 192 + ch * 96 + seg * 8;
            cp16(sBH + so, Wh + g);
            cp16(sBL + so, Wl + g);
        }
    };
    load_chunk(0); cp_commit();
    load_chunk(1); cp_commit();

    float acc[6][4];
    #pragma unroll
    for (int nt = 0; nt < 6; nt++)
        #pragma unroll
        for (int q = 0; q < 4; q++) acc[nt][q] = 0.f;

    uint32_t aoff = (wm + (lane & 15)) * GF_ASTR + (lane >> 4) * 16;
    uint32_t bbase = (wn + (lane & 7) + ((lane >> 4) << 3)) * GF_ASTR + (((lane >> 3) & 1) * 16);

    auto compute_range = [&](int k0, int k1) {
        #pragma unroll
        for (int ks = k0; ks < k1; ks++) {
            uint32_t ko = ks * 32;
            uint32_t ah[4], al[4], bh[3][4], bl[3][4];
            ldmx4(ah, sAH + aoff + ko);
            ldmx4(al, sAL + aoff + ko);
            #pragma unroll
            for (int p = 0; p < 3; p++) {
                uint32_t bo = bbase + p * 16 * GF_ASTR + ko;
                ldmx4(bh[p], sBH + bo);
                ldmx4(bl[p], sBL + bo);
            }
            #pragma unroll
            for (int nt = 0; nt < 6; nt++) {
                const uint32_t* b2h = &bh[nt >> 1][(nt & 1) * 2];
                const uint32_t* b2l = &bl[nt >> 1][(nt & 1) * 2];
                mma16816(acc[nt], ah, b2h);
                mma16816(acc[nt], ah, b2l);
                mma16816(acc[nt], al, b2h);
            }
        }
    };

    cp_wait<1>(); __syncthreads();
    compute_range(0, 6);
    cp_wait<0>(); __syncthreads();
    compute_range(6, 12);

    int rb = m0 + wm + (lane >> 2);
    int cb = wn + (lane & 3) * 2;
    #pragma unroll
    for (int nt = 0; nt < 6; nt++) {
        int cc = cb + nt * 8;
        *reinterpret_cast<float2*>(&S[(size_t)rb * HID + cc]) =
            make_float2(acc[nt][0], acc[nt][1]);
        *reinterpret_cast<float2*>(&S[(size_t)(rb + 8) * HID + cc]) =
            make_float2(acc[nt][2], acc[nt][3]);
    }
}

// ---------------- fast aggregation: float4 gathers, one warp per row ----------------
template <int MODE>
__global__ __launch_bounds__(256) void agg2(const float* __restrict__ S,
                                            const float* __restrict__ bias,
                                            const float* __restrict__ resptr,
                                            float* __restrict__ fbout,
                                            __nv_bfloat16* __restrict__ ohi,
                                            __nv_bfloat16* __restrict__ olo,
                                            const int* __restrict__ nidx,
                                            const float* __restrict__ nval,
                                            const int* __restrict__ ncnt)
{
    int row = (blockIdx.x * blockDim.x + threadIdx.x) >> 5;
    int lane = threadIdx.x & 31;
    if (row >= NN) return;
    int half = lane >> 4, sl = lane & 15;
    int cnt = ncnt[row];
    const int* ni = nidx + (size_t)row * MAXN;
    const float* nv = nval + (size_t)row * MAXN;

    float a0 = 0.f, a1 = 0.f, a2 = 0.f, a3 = 0.f;
    float b0 = 0.f, b1 = 0.f, b2 = 0.f, b3 = 0.f;
    for (int i = 0; i < cnt; i += 4) {
        int4   ji = *reinterpret_cast<const int4*>(ni + i);
        float4 wv = *reinterpret_cast<const float4*>(nv + i);
        int   nA = half ? ji.y : ji.x;  float wA = half ? wv.y : wv.x;
        int   nB = half ? ji.w : ji.z;  float wB = half ? wv.w : wv.z;
        float4 vA = *reinterpret_cast<const float4*>(S + (size_t)nA * HID + 4 * sl);
        float4 vB = *reinterpret_cast<const float4*>(S + (size_t)nB * HID + 4 * sl);
        a0 = fmaf(wA, vA.x, a0); a1 = fmaf(wA, vA.y, a1);
        a2 = fmaf(wA, vA.z, a2); a3 = fmaf(wA, vA.w, a3);
        b0 = fmaf(wB, vB.x, b0); b1 = fmaf(wB, vB.y, b1);
        b2 = fmaf(wB, vB.z, b2); b3 = fmaf(wB, vB.w, b3);
    }
    a0 += b0; a1 += b1; a2 += b2; a3 += b3;
    a0 += __shfl_xor_sync(0xffffffffu, a0, 16);
    a1 += __shfl_xor_sync(0xffffffffu, a1, 16);
    a2 += __shfl_xor_sync(0xffffffffu, a2, 16);
    a3 += __shfl_xor_sync(0xffffffffu, a3, 16);

    size_t rbase = (size_t)row * HID;

    if (lane < 16) {
        int c = 4 * sl;
        float4 bs = *reinterpret_cast<const float4*>(bias + c);
        float t0 = fmaxf(a0 + bs.x, 0.f);
        float t1 = fmaxf(a1 + bs.y, 0.f);
        float t2 = fmaxf(a2 + bs.z, 0.f);
        float t3 = fmaxf(a3 + bs.w, 0.f);
        if (MODE == 1) {
            float4 rv = *reinterpret_cast<const float4*>(resptr + (size_t)row * INF + c);
            t0 = (rv.x + t0) * 0.5f; t1 = (rv.y + t1) * 0.5f;
            t2 = (rv.z + t2) * 0.5f; t3 = (rv.w + t3) * 0.5f;
        }
        if (MODE == 2) {
            float4 rv = *reinterpret_cast<const float4*>(resptr + rbase + c);
            t0 = (rv.x + t0) * 0.5f; t1 = (rv.y + t1) * 0.5f;
            t2 = (rv.z + t2) * 0.5f; t3 = (rv.w + t3) * 0.5f;
        }
        if (MODE >= 1)
            *reinterpret_cast<float4*>(fbout + rbase + c) = make_float4(t0, t1, t2, t3);
        __nv_bfloat16 h0 = __float2bfloat16(t0), h1 = __float2bfloat16(t1);
        __nv_bfloat16 h2 = __float2bfloat16(t2), h3 = __float2bfloat16(t3);
        __nv_bfloat162 hp0; hp0.x = h0; hp0.y = h1;
        __nv_bfloat162 hp1; hp1.x = h2; hp1.y = h3;
        *reinterpret_cast<__nv_bfloat162*>(ohi + rbase + c)     = hp0;
        *reinterpret_cast<__nv_bfloat162*>(ohi + rbase + c + 2) = hp1;
        __nv_bfloat162 lp0, lp1;
        lp0.x = __float2bfloat16(t0 - __bfloat162float(h0));
        lp0.y = __float2bfloat16(t1 - __bfloat162float(h1));
        lp1.x = __float2bfloat16(t2 - __bfloat162float(h2));
        lp1.y = __float2bfloat16(t3 - __bfloat162float(h3));
        *reinterpret_cast<__nv_bfloat162*>(olo + rbase + c)     = lp0;
        *reinterpret_cast<__nv_bfloat162*>(olo + rbase + c + 2) = lp1;
    }

    {
        int c = 64 + 4 * lane;
        float4 sv = *reinterpret_cast<const float4*>(S + rbase + c);
        float4 bs = *reinterpret_cast<const float4*>(bias + c);
        float t0 = fmaxf(sv.x + bs.x, 0.f);
        float t1 = fmaxf(sv.y + bs.y, 0.f);
        float t2 = fmaxf(sv.z + bs.z, 0.f);
        float t3 = fmaxf(sv.w + bs.w, 0.f);
        if (MODE == 1) {
            float4 rv = *reinterpret_cast<const float4*>(resptr + (size_t)row * INF + c);
            t0 = (rv.x + t0) * 0.5f; t1 = (rv.y + t1) * 0.5f;
            t2 = (rv.z + t2) * 0.5f; t3 = (rv.w + t3) * 0.5f;
        }
        if (MODE == 2) {
            float4 rv = *reinterpret_cast<const float4*>(resptr + rbase + c);
            t0 = (rv.x + t0) * 0.5f; t1 = (rv.y + t1) * 0.5f;
            t2 = (rv.z + t2) * 0.5f; t3 = (rv.w + t3) * 0.5f;
        }
        if (MODE >= 1)
            *reinterpret_cast<float4*>(fbout + rbase + c) = make_float4(t0, t1, t2, t3);
        __nv_bfloat16 h0 = __float2bfloat16(t0), h1 = __float2bfloat16(t1);
        __nv_bfloat16 h2 = __float2bfloat16(t2), h3 = __float2bfloat16(t3);
        __nv_bfloat162 hp0; hp0.x = h0; hp0.y = h1;
        __nv_bfloat162 hp1; hp1.x = h2; hp1.y = h3;
        *reinterpret_cast<__nv_bfloat162*>(ohi + rbase + c)     = hp0;
        *reinterpret_cast<__nv_bfloat162*>(ohi + rbase + c + 2) = hp1;
        __nv_bfloat162 lp0, lp1;
        lp0.x = __float2bfloat16(t0 - __bfloat162float(h0));
        lp0.y = __float2bfloat16(t1 - __bfloat162float(h1));
        lp1.x = __float2bfloat16(t2 - __bfloat162float(h2));
        lp1.y = __float2bfloat16(t3 - __bfloat162float(h3));
        *reinterpret_cast<__nv_bfloat162*>(olo + rbase + c)     = lp0;
        *reinterpret_cast<__nv_bfloat162*>(olo + rbase + c + 2) = lp1;
    }
}

// ---------------- fused tail: agg gc13 (+res fb) -> fb,feat_out ; sup3 = feat @ W_out ----
__global__ __launch_bounds__(256) void tail_fused(const float* __restrict__ S,
                                                  const float* __restrict__ bias,
                                                  float* __restrict__ fb,
                                                  float* __restrict__ feat_out,
                                                  const float* __restrict__ W_out,
                                                  float* __restrict__ sup3,
                                                  const int* __restrict__ nidx,
                                                  const float* __restrict__ nval,
                                                  const int* __restrict__ ncnt)
{
    int row = (blockIdx.x * blockDim.x + threadIdx.x) >> 5;
    int lane = threadIdx.x & 31;
    if (row >= NN) return;
    int cnt = ncnt[row];
    const int* ni = nidx + (size_t)row * MAXN;
    const float* nv = nval + (size_t)row * MAXN;
    float acc0 = 0.f, acc1 = 0.f, e0 = 0.f, e1 = 0.f;
    for (int i = 0; i < cnt; i += 4) {
        int4   ji = *reinterpret_cast<const int4*>(ni + i);
        float4 ui = *reinterpret_cast<const float4*>(nv + i);
        const float* s0 = S + (size_t)ji.x * HID;
        const float* s1 = S + (size_t)ji.y * HID;
        const float* s2 = S + (size_t)ji.z * HID;
        const float* s3 = S + (size_t)ji.w * HID;
        acc0 = fmaf(ui.x, s0[lane], acc0);  acc1 = fmaf(ui.x, s0[lane + 32], acc1);
        e0   = fmaf(ui.y, s1[lane], e0);    e1   = fmaf(ui.y, s1[lane + 32], e1);
        acc0 = fmaf(ui.z, s2[lane], acc0);  acc1 = fmaf(ui.z, s2[lane + 32], acc1);
        e0   = fmaf(ui.w, s3[lane], e0);    e1   = fmaf(ui.w, s3[lane + 32], e1);
    }
    acc0 += e0; acc1 += e1;

    float w0s = 0.f, w1s = 0.f, w2s = 0.f;
    size_t rbase = (size_t)row * HID;
    #pragma unroll
    for (int j = 0; j < 6; j++) {
        int c = 32 * j + lane;
        float t = (j == 0) ? acc0 : (j == 1) ? acc1 : S[rbase + c];
        t += bias[c];
        t = fmaxf(t, 0.f);
        t = (fb[rbase + c] + t) * 0.5f;
        fb[rbase + c] = t;
        feat_out[rbase + c] = t;
        w0s = fmaf(t, W_out[c * 3 + 0], w0s);
        w1s = fmaf(t, W_out[c * 3 + 1], w1s);
        w2s = fmaf(t, W_out[c * 3 + 2], w2s);
    }
    #pragma unroll
    for (int d = 16; d; d >>= 1) {
        w0s += __shfl_xor_sync(0xffffffffu, w0s, d);
        w1s += __shfl_xor_sync(0xffffffffu, w1s, d);
        w2s += __shfl_xor_sync(0xffffffffu, w2s, d);
    }
    if (lane == 0) {
        sup3[row * 3 + 0] = w0s;
        sup3[row * 3 + 1] = w1s;
        sup3[row * 3 + 2] = w2s;
    }
}

// ---------------- standalone aggregation (coords) ----------------
__global__ __launch_bounds__(256) void agg_kernel(const float* __restrict__ S,
                                                  const float* __restrict__ bias,
                                                  float* __restrict__ out,
                                                  const int* __restrict__ nidx,
                                                  const float* __restrict__ nval,
                                                  const int* __restrict__ ncnt,
                                                  int n_out, int side)
{
    int warp = (blockIdx.x * blockDim.x + threadIdx.x) >> 5;
    int lane = threadIdx.x & 31;
    if (warp >= NN) return;
    int cnt = ncnt[warp];
    const int* ni = nidx + (size_t)warp * MAXN;
    const float* nv = nval + (size_t)warp * MAXN;
    float acc0 = 0.f;
    for (int i = 0; i < cnt; i++) {
        if (lane < side) acc0 = fmaf(nv[i], S[(size_t)ni[i] * n_out + lane], acc0);
    }
    if (lane < n_out) {
        float t = (lane < side) ? acc0 : S[(size_t)warp * n_out + lane];
        t += bias[lane];
        out[(size_t)warp * n_out + lane] = t;
    }
}

extern "C" void kernel_launch(void* const* d_in, const int* in_sizes, int n_in,
                              void* d_out, int out_size)
{
    const float* features = (const float*)d_in[0];
    const float* adj      = (const float*)d_in[1];
    const float* W1       = (const float*)d_in[2];
    const float* b1       = (const float*)d_in[3];
    const float* W_mid    = (const float*)d_in[4];
    const float* b_mid    = (const float*)d_in[5];
    const float* W_out    = (const float*)d_in[6];
    const float* b_out    = (const float*)d_in[7];
    float* out = (float*)d_out;
    float* coords   = out;
    float* feat_out = out + NN * 3;

    float *sa, *sbuf, *fb, *sup3, *nval;
    __nv_bfloat16 *xhi, *xlo, *whi, *wlo;
    int *nidx, *ncnt;
    cudaGetSymbolAddress((void**)&sa,   g_supA);
    cudaGetSymbolAddress((void**)&sbuf, g_supB);
    cudaGetSymbolAddress((void**)&fb,   g_featbuf);
    cudaGetSymbolAddress((void**)&sup3, g_sup3);
    cudaGetSymbolAddress((void**)&xhi,  g_xhi);
    cudaGetSymbolAddress((void**)&xlo,  g_xlo);
    cudaGetSymbolAddress((void**)&whi,  g_wthi);
    cudaGetSymbolAddress((void**)&wlo,  g_wtlo);
    cudaGetSymbolAddress((void**)&nidx, g_nidx);
    cudaGetSymbolAddress((void**)&nval, g_nval);
    cudaGetSymbolAddress((void**)&ncnt, g_ncnt);

    cudaFuncSetAttribute(gemm_os, cudaFuncAttributeMaxDynamicSharedMemorySize, SMEM_K256);
    cudaFuncSetAttribute(gemm_full, cudaFuncAttributeMaxDynamicSharedMemorySize, GF_SMEM);

    build_csr<<<NN / 8, 256>>>(adj, nidx, nval, ncnt);
    convert_weights<<<(WT_TOTAL + 255) / 256, 256>>>(W1, W_mid, whi, wlo);
    convert_features<<<(NN * INF + 255) / 256, 256>>>(features, xhi, xlo);

    auto woff = [](int i) { return (size_t)192 * 256 + (size_t)i * 192 * 192; };

    dim3 g1(NN / BM, HID / BN);
    gemm_os<<<g1, 256, SMEM_K256>>>(xhi, xlo, whi, wlo, sa);

    agg2<0><<<NN / 8, 256>>>(sa, b1, nullptr, nullptr, xhi, xlo, nidx, nval, ncnt);
    gemm_full<<<NN / 64, 512, GF_SMEM>>>(xhi, xlo, whi + woff(0), wlo + woff(0), sbuf);
    agg2<1><<<NN / 8, 256>>>(sbuf, b_mid + 0, features, fb, xhi, xlo, nidx, nval, ncnt);
    gemm_full<<<NN / 64, 512, GF_SMEM>>>(xhi, xlo, whi + woff(1), wlo + woff(1), sa);

    float* cur = sa; float* nxt = sbuf;
    for (int p = 0; p < 5; p++) {
        int bi = 1 + 2 * p;
        agg2<0><<<NN / 8, 256>>>(cur, b_mid + (size_t)bi * HID, nullptr, nullptr,
                                 xhi, xlo, nidx, nval, ncnt);
        gemm_full<<<NN / 64, 512, GF_SMEM>>>(xhi, xlo, whi + woff(bi + 1), wlo + woff(bi + 1), nxt);
        { float* t = cur; cur = nxt; nxt = t; }
        agg2<2><<<NN / 8, 256>>>(cur, b_mid + (size_t)(bi + 1) * HID, fb, fb,
                                 xhi, xlo, nidx, nval, ncnt);
        gemm_full<<<NN / 64, 512, GF_SMEM>>>(xhi, xlo, whi + woff(bi + 2), wlo + woff(bi + 2), nxt);
        { float* t = cur; cur = nxt; nxt = t; }
    }

    // fused tail: agg gc13 + residual + feat_out + sup3 = feat @ W_out
    tail_fused<<<NN / 8, 256>>>(cur, b_mid + (size_t)11 * HID, fb, feat_out,
                                W_out, sup3, nidx, nval, ncnt);
    // coords = agg(sup3, side=2) + b_out
    agg_kernel<<<NN / 8, 256>>>(sup3, b_out, coords, nidx, nval, ncnt, 3, 2);
}

// round 9
// speedup vs baseline: 1.8083x; 1.0014x over previous
#include <cuda_runtime.h>
#include <cuda_bf16.h>
#include <cstdint>
#include <cstddef>

#define NN   8192
#define HID  192
#define INF  256
#define MAXN 128

// ---------------- device scratch ----------------
__device__ float g_supA[NN * HID];
__device__ float g_supB[NN * HID];
__device__ float g_featbuf[NN * HID];
__device__ float g_sup3[NN * 3];
__device__ __nv_bfloat16 g_xhi[NN * INF];
__device__ __nv_bfloat16 g_xlo[NN * INF];
#define WT_TOTAL (192*256 + 12*192*192)
__device__ __nv_bfloat16 g_wthi[WT_TOTAL];
__device__ __nv_bfloat16 g_wtlo[WT_TOTAL];
__device__ int   g_nidx[NN * MAXN];
__device__ float g_nval[NN * MAXN];
__device__ int   g_ncnt[NN];

// ---------------- PTX helpers (compute_103-safe) ----------------
__device__ __forceinline__ uint32_t smem_u32(const void* p) {
    uint32_t a;
    asm("{ .reg .u64 t; cvta.to.shared.u64 t, %1; cvt.u32.u64 %0, t; }" : "=r"(a) : "l"(p));
    return a;
}
__device__ __forceinline__ void cp16(uint32_t d, const void* s) {
    asm volatile("cp.async.cg.shared.global [%0], [%1], 16;" :: "r"(d), "l"(s));
}
__device__ __forceinline__ void cp_commit() {
    asm volatile("cp.async.commit_group;" ::: "memory");
}
template <int N> __device__ __forceinline__ void cp_wait() {
    asm volatile("cp.async.wait_group %0;" :: "n"(N) : "memory");
}
__device__ __forceinline__ void ldmx4(uint32_t* r, uint32_t a) {
    asm volatile("ldmatrix.sync.aligned.m8n8.x4.shared.b16 {%0,%1,%2,%3}, [%4];"
        : "=r"(r[0]), "=r"(r[1]), "=r"(r[2]), "=r"(r[3]) : "r"(a));
}
__device__ __forceinline__ void mma16816(float* d, const uint32_t* a, const uint32_t* b) {
    asm volatile("mma.sync.aligned.m16n8k16.row.col.f32.bf16.bf16.f32 "
        "{%0,%1,%2,%3}, {%4,%5,%6,%7}, {%8,%9}, {%0,%1,%2,%3};"
        : "+f"(d[0]), "+f"(d[1]), "+f"(d[2]), "+f"(d[3])
        : "r"(a[0]), "r"(a[1]), "r"(a[2]), "r"(a[3]), "r"(b[0]), "r"(b[1]));
}

// ---------------- CSR extraction (pads each row to multiple of 4) ----------------
__global__ __launch_bounds__(256) void build_csr(const float* __restrict__ adj,
                                                 int* __restrict__ nidx,
                                                 float* __restrict__ nval,
                                                 int* __restrict__ ncnt)
{
    int warp = (blockIdx.x * blockDim.x + threadIdx.x) >> 5;
    int lane = threadIdx.x & 31;
    if (warp >= NN) return;
    const float4* row = reinterpret_cast<const float4*>(adj + (size_t)warp * NN);
    int* my_idx = nidx + (size_t)warp * MAXN;
    float* my_val = nval + (size_t)warp * MAXN;
    int count = 0;
    for (int it = 0; it < NN / 128; it++) {
        float4 v = row[it * 32 + lane];
        int c0 = it * 128 + lane * 4;
        int my = (v.x != 0.f) + (v.y != 0.f) + (v.z != 0.f) + (v.w != 0.f);
        int inc = my;
        #pragma unroll
        for (int d = 1; d < 32; d <<= 1) {
            int t = __shfl_up_sync(0xffffffffu, inc, d);
            if (lane >= d) inc += t;
        }
        int total = __shfl_sync(0xffffffffu, inc, 31);
        int pos = count + inc - my;
        if (v.x != 0.f) { if (pos < MAXN) { my_idx[pos] = c0;     my_val[pos] = v.x; } pos++; }
        if (v.y != 0.f) { if (pos < MAXN) { my_idx[pos] = c0 + 1; my_val[pos] = v.y; } pos++; }
        if (v.z != 0.f) { if (pos < MAXN) { my_idx[pos] = c0 + 2; my_val[pos] = v.z; } pos++; }
        if (v.w != 0.f) { if (pos < MAXN) { my_idx[pos] = c0 + 3; my_val[pos] = v.w; } pos++; }
        count += total;
    }
    if (count > MAXN) count = MAXN;
    int padded = (count + 3) & ~3;
    if (padded > MAXN) padded = MAXN;
    for (int s = count + lane; s < padded; s += 32) { my_idx[s] = 0; my_val[s] = 0.f; }
    if (lane == 0) ncnt[warp] = padded;
}

// ---------------- weight / feature conversion ----------------
__global__ __launch_bounds__(256) void convert_weights(const float* __restrict__ W1,
                                                       const float* __restrict__ W_mid,
                                                       __nv_bfloat16* __restrict__ whi,
                                                       __nv_bfloat16* __restrict__ wlo)
{
    int idx = blockIdx.x * blockDim.x + threadIdx.x;
    if (idx >= WT_TOTAL) return;
    float w;
    if (idx < 192 * 256) {
        int n = idx / 256, k = idx % 256;
        w = W1[k * 192 + n];
    } else {
        int rel = idx - 192 * 256;
        int i = rel / (192 * 192);
        int r = rel % (192 * 192);
        int n = r / 192, k = r % 192;
        w = W_mid[(size_t)i * 192 * 192 + k * 192 + n];
    }
    __nv_bfloat16 h = __float2bfloat16(w);
    whi[idx] = h;
    wlo[idx] = __float2bfloat16(w - __bfloat162float(h));
}

__global__ __launch_bounds__(256) void convert_features(const float* __restrict__ f,
                                                        __nv_bfloat16* __restrict__ xhi,
                                                        __nv_bfloat16* __restrict__ xlo)
{
    int idx = blockIdx.x * blockDim.x + threadIdx.x;
    if (idx >= NN * INF) return;
    float v = f[idx];
    __nv_bfloat16 h = __float2bfloat16(v);
    xhi[idx] = h;
    xlo[idx] = __float2bfloat16(v - __bfloat162float(h));
}

// ---------------- gc1: 2-chunk pipelined split-bf16 HMMA, K=256, BM=BN=64 ----------------
#define BM 64
#define BN 64
__global__ void __launch_bounds__(256, 1)
gemm_os(const __nv_bfloat16* __restrict__ Xh, const __nv_bfloat16* __restrict__ Xl,
        const __nv_bfloat16* __restrict__ Wh, const __nv_bfloat16* __restrict__ Wl,
        float* __restrict__ S)
{
    constexpr int KK = 256;
    constexpr int ASTR = KK * 2 + 16;
    constexpr int SLAB = BM * ASTR;
    extern __shared__ char smem[];
    uint32_t sb = smem_u32(smem);
    const uint32_t sAH = sb, sAL = sb + SLAB, sBH = sb + 2 * SLAB, sBL = sb + 3 * SLAB;

    int tid = threadIdx.x;
    int m0 = blockIdx.x * BM;
    int n0 = blockIdx.y * BN;
    int w = tid >> 5, lane = tid & 31;
    int wm = (w & 3) * 16;
    int wn = (w >> 2) * 32;

    auto load_chunk = [&](int ch) {   // 128 cols = 16 segs per row
        #pragma unroll
        for (int v = tid; v < BM * 16; v += 256) {
            int row = v >> 4, seg = v & 15;
            uint32_t so = row * ASTR + (ch * 16 + seg) * 16;
            size_t ga = (size_t)(m0 + row) * KK + ch * 128 + seg * 8;
            size_t gb = (size_t)(n0 + row) * KK + ch * 128 + seg * 8;
            cp16(sAH + so, Xh + ga);
            cp16(sAL + so, Xl + ga);
            cp16(sBH + so, Wh + gb);
            cp16(sBL + so, Wl + gb);
        }
    };
    load_chunk(0); cp_commit();
    load_chunk(1); cp_commit();

    float acc[4][4];
    #pragma unroll
    for (int nt = 0; nt < 4; nt++)
        #pragma unroll
        for (int q = 0; q < 4; q++) acc[nt][q] = 0.f;

    uint32_t aoff = (wm + (lane & 15)) * ASTR + (lane >> 4) * 16;
    uint32_t boff0 = (wn + (lane & 7) + ((lane >> 4) << 3)) * ASTR + (((lane >> 3) & 1) * 16);
    uint32_t boff1 = boff0 + 16 * ASTR;

    auto compute_range = [&](int k0, int k1) {
        #pragma unroll
        for (int ks = k0; ks < k1; ks++) {
            uint32_t ko = ks * 32;
            uint32_t ah[4], al[4], bh[2][4], bl[2][4];
            ldmx4(ah, sAH + aoff + ko);
            ldmx4(al, sAL + aoff + ko);
            ldmx4(bh[0], sBH + boff0 + ko);
            ldmx4(bl[0], sBL + boff0 + ko);
            ldmx4(bh[1], sBH + boff1 + ko);
            ldmx4(bl[1], sBL + boff1 + ko);
            #pragma unroll
            for (int nt = 0; nt < 4; nt++) {
                const uint32_t* b2h = &bh[nt >> 1][(nt & 1) * 2];
                const uint32_t* b2l = &bl[nt >> 1][(nt & 1) * 2];
                mma16816(acc[nt], ah, b2h);
                mma16816(acc[nt], ah, b2l);
                mma16816(acc[nt], al, b2h);
            }
        }
    };

    cp_wait<1>(); __syncthreads();
    compute_range(0, 8);
    cp_wait<0>(); __syncthreads();
    compute_range(8, 16);

    int rb = m0 + wm + (lane >> 2);
    int cb = n0 + wn + (lane & 3) * 2;
    #pragma unroll
    for (int nt = 0; nt < 4; nt++) {
        int cc = cb + nt * 8;
        *reinterpret_cast<float2*>(&S[(size_t)rb * HID + cc]) =
            make_float2(acc[nt][0], acc[nt][1]);
        *reinterpret_cast<float2*>(&S[(size_t)(rb + 8) * HID + cc]) =
            make_float2(acc[nt][2], acc[nt][3]);
    }
}
#define SMEM_K256 (4 * BM * (256 * 2 + 16))

// ---------------- mid-layer GEMM: BM=64, BN=192, K=192, 512 thr, 2-chunk pipeline ----
#define GF_ASTR 400
#define GF_ASLAB (64 * GF_ASTR)
#define GF_BSLAB (192 * GF_ASTR)
#define GF_SMEM (2 * GF_ASLAB + 2 * GF_BSLAB)   // 204800

__global__ void __launch_bounds__(512, 1)
gemm_full(const __nv_bfloat16* __restrict__ Xh, const __nv_bfloat16* __restrict__ Xl,
          const __nv_bfloat16* __restrict__ Wh, const __nv_bfloat16* __restrict__ Wl,
          float* __restrict__ S)
{
    extern __shared__ char smem[];
    uint32_t sb = smem_u32(smem);
    const uint32_t sAH = sb, sAL = sb + GF_ASLAB;
    const uint32_t sBH = sb + 2 * GF_ASLAB, sBL = sb + 2 * GF_ASLAB + GF_BSLAB;

    int tid = threadIdx.x;
    int m0 = blockIdx.x * 64;
    int w = tid >> 5, lane = tid & 31;
    int wm = (w & 3) * 16;
    int wn = (w >> 2) * 48;

    auto load_chunk = [&](int ch) {   // 96 cols = 12 segs per row
        #pragma unroll
        for (int v = tid; v < 64 * 12; v += 512) {
            int row = v / 12, seg = v % 12;
            uint32_t so = row * GF_ASTR + (ch * 12 + seg) * 16;
            size_t g = (size_t)(m0 + row) * 192 + ch * 96 + seg * 8;
            cp16(sAH + so, Xh + g);
            cp16(sAL + so, Xl + g);
        }
        #pragma unroll
        for (int v = tid; v < 192 * 12; v += 512) {
            int row = v / 12, seg = v % 12;
            uint32_t so = row * GF_ASTR + (ch * 12 + seg) * 16;
            size_t g = (size_t)row * 192 + ch * 96 + seg * 8;
            cp16(sBH + so, Wh + g);
            cp16(sBL + so, Wl + g);
        }
    };
    load_chunk(0); cp_commit();
    load_chunk(1); cp_commit();

    float acc[6][4];
    #pragma unroll
    for (int nt = 0; nt < 6; nt++)
        #pragma unroll
        for (int q = 0; q < 4; q++) acc[nt][q] = 0.f;

    uint32_t aoff = (wm + (lane & 15)) * GF_ASTR + (lane >> 4) * 16;
    uint32_t bbase = (wn + (lane & 7) + ((lane >> 4) << 3)) * GF_ASTR + (((lane >> 3) & 1) * 16);

    auto compute_range = [&](int k0, int k1) {
        #pragma unroll
        for (int ks = k0; ks < k1; ks++) {
            uint32_t ko = ks * 32;
            uint32_t ah[4], al[4], bh[3][4], bl[3][4];
            ldmx4(ah, sAH + aoff + ko);
            ldmx4(al, sAL + aoff + ko);
            #pragma unroll
            for (int p = 0; p < 3; p++) {
                uint32_t bo = bbase + p * 16 * GF_ASTR + ko;
                ldmx4(bh[p], sBH + bo);
                ldmx4(bl[p], sBL + bo);
            }
            #pragma unroll
            for (int nt = 0; nt < 6; nt++) {
                const uint32_t* b2h = &bh[nt >> 1][(nt & 1) * 2];
                const uint32_t* b2l = &bl[nt >> 1][(nt & 1) * 2];
                mma16816(acc[nt], ah, b2h);
                mma16816(acc[nt], ah, b2l);
                mma16816(acc[nt], al, b2h);
            }
        }
    };

    cp_wait<1>(); __syncthreads();
    compute_range(0, 6);
    cp_wait<0>(); __syncthreads();
    compute_range(6, 12);

    int rb = m0 + wm + (lane >> 2);
    int cb = wn + (lane & 3) * 2;
    #pragma unroll
    for (int nt = 0; nt < 6; nt++) {
        int cc = cb + nt * 8;
        *reinterpret_cast<float2*>(&S[(size_t)rb * HID + cc]) =
            make_float2(acc[nt][0], acc[nt][1]);
        *reinterpret_cast<float2*>(&S[(size_t)(rb + 8) * HID + cc]) =
            make_float2(acc[nt][2], acc[nt][3]);
    }
}

// ---------------- fast aggregation: float4 gathers, one warp per row ----------------
template <int MODE>
__global__ __launch_bounds__(256) void agg2(const float* __restrict__ S,
                                            const float* __restrict__ bias,
                                            const float* __restrict__ resptr,
                                            float* __restrict__ fbout,
                                            __nv_bfloat16* __restrict__ ohi,
                                            __nv_bfloat16* __restrict__ olo,
                                            const int* __restrict__ nidx,
                                            const float* __restrict__ nval,
                                            const int* __restrict__ ncnt)
{
    int row = (blockIdx.x * blockDim.x + threadIdx.x) >> 5;
    int lane = threadIdx.x & 31;
    if (row >= NN) return;
    int half = lane >> 4, sl = lane & 15;
    int cnt = ncnt[row];
    const int* ni = nidx + (size_t)row * MAXN;
    const float* nv = nval + (size_t)row * MAXN;

    float a0 = 0.f, a1 = 0.f, a2 = 0.f, a3 = 0.f;
    float b0 = 0.f, b1 = 0.f, b2 = 0.f, b3 = 0.f;
    for (int i = 0; i < cnt; i += 4) {
        int4   ji = *reinterpret_cast<const int4*>(ni + i);
        float4 wv = *reinterpret_cast<const float4*>(nv + i);
        int   nA = half ? ji.y : ji.x;  float wA = half ? wv.y : wv.x;
        int   nB = half ? ji.w : ji.z;  float wB = half ? wv.w : wv.z;
        float4 vA = *reinterpret_cast<const float4*>(S + (size_t)nA * HID + 4 * sl);
        float4 vB = *reinterpret_cast<const float4*>(S + (size_t)nB * HID + 4 * sl);
        a0 = fmaf(wA, vA.x, a0); a1 = fmaf(wA, vA.y, a1);
        a2 = fmaf(wA, vA.z, a2); a3 = fmaf(wA, vA.w, a3);
        b0 = fmaf(wB, vB.x, b0); b1 = fmaf(wB, vB.y, b1);
        b2 = fmaf(wB, vB.z, b2); b3 = fmaf(wB, vB.w, b3);
    }
    a0 += b0; a1 += b1; a2 += b2; a3 += b3;
    a0 += __shfl_xor_sync(0xffffffffu, a0, 16);
    a1 += __shfl_xor_sync(0xffffffffu, a1, 16);
    a2 += __shfl_xor_sync(0xffffffffu, a2, 16);
    a3 += __shfl_xor_sync(0xffffffffu, a3, 16);

    size_t rbase = (size_t)row * HID;

    if (lane < 16) {
        int c = 4 * sl;
        float4 bs = *reinterpret_cast<const float4*>(bias + c);
        float t0 = fmaxf(a0 + bs.x, 0.f);
        float t1 = fmaxf(a1 + bs.y, 0.f);
        float t2 = fmaxf(a2 + bs.z, 0.f);
        float t3 = fmaxf(a3 + bs.w, 0.f);
        if (MODE == 1) {
            float4 rv = *reinterpret_cast<const float4*>(resptr + (size_t)row * INF + c);
            t0 = (rv.x + t0) * 0.5f; t1 = (rv.y + t1) * 0.5f;
            t2 = (rv.z + t2) * 0.5f; t3 = (rv.w + t3) * 0.5f;
        }
        if (MODE == 2) {
            float4 rv = *reinterpret_cast<const float4*>(resptr + rbase + c);
            t0 = (rv.x + t0) * 0.5f; t1 = (rv.y + t1) * 0.5f;
            t2 = (rv.z + t2) * 0.5f; t3 = (rv.w + t3) * 0.5f;
        }
        if (MODE >= 1)
            *reinterpret_cast<float4*>(fbout + rbase + c) = make_float4(t0, t1, t2, t3);
        __nv_bfloat16 h0 = __float2bfloat16(t0), h1 = __float2bfloat16(t1);
        __nv_bfloat16 h2 = __float2bfloat16(t2), h3 = __float2bfloat16(t3);
        __nv_bfloat162 hp0; hp0.x = h0; hp0.y = h1;
        __nv_bfloat162 hp1; hp1.x = h2; hp1.y = h3;
        *reinterpret_cast<__nv_bfloat162*>(ohi + rbase + c)     = hp0;
        *reinterpret_cast<__nv_bfloat162*>(ohi + rbase + c + 2) = hp1;
        __nv_bfloat162 lp0, lp1;
        lp0.x = __float2bfloat16(t0 - __bfloat162float(h0));
        lp0.y = __float2bfloat16(t1 - __bfloat162float(h1));
        lp1.x = __float2bfloat16(t2 - __bfloat162float(h2));
        lp1.y = __float2bfloat16(t3 - __bfloat162float(h3));
        *reinterpret_cast<__nv_bfloat162*>(olo + rbase + c)     = lp0;
        *reinterpret_cast<__nv_bfloat162*>(olo + rbase + c + 2) = lp1;
    }

    {
        int c = 64 + 4 * lane;
        float4 sv = *reinterpret_cast<const float4*>(S + rbase + c);
        float4 bs = *reinterpret_cast<const float4*>(bias + c);
        float t0 = fmaxf(sv.x + bs.x, 0.f);
        float t1 = fmaxf(sv.y + bs.y, 0.f);
        float t2 = fmaxf(sv.z + bs.z, 0.f);
        float t3 = fmaxf(sv.w + bs.w, 0.f);
        if (MODE == 1) {
            float4 rv = *reinterpret_cast<const float4*>(resptr + (size_t)row * INF + c);
            t0 = (rv.x + t0) * 0.5f; t1 = (rv.y + t1) * 0.5f;
            t2 = (rv.z + t2) * 0.5f; t3 = (rv.w + t3) * 0.5f;
        }
        if (MODE == 2) {
            float4 rv = *reinterpret_cast<const float4*>(resptr + rbase + c);
            t0 = (rv.x + t0) * 0.5f; t1 = (rv.y + t1) * 0.5f;
            t2 = (rv.z + t2) * 0.5f; t3 = (rv.w + t3) * 0.5f;
        }
        if (MODE >= 1)
            *reinterpret_cast<float4*>(fbout + rbase + c) = make_float4(t0, t1, t2, t3);
        __nv_bfloat16 h0 = __float2bfloat16(t0), h1 = __float2bfloat16(t1);
        __nv_bfloat16 h2 = __float2bfloat16(t2), h3 = __float2bfloat16(t3);
        __nv_bfloat162 hp0; hp0.x = h0; hp0.y = h1;
        __nv_bfloat162 hp1; hp1.x = h2; hp1.y = h3;
        *reinterpret_cast<__nv_bfloat162*>(ohi + rbase + c)     = hp0;
        *reinterpret_cast<__nv_bfloat162*>(ohi + rbase + c + 2) = hp1;
        __nv_bfloat162 lp0, lp1;
        lp0.x = __float2bfloat16(t0 - __bfloat162float(h0));
        lp0.y = __float2bfloat16(t1 - __bfloat162float(h1));
        lp1.x = __float2bfloat16(t2 - __bfloat162float(h2));
        lp1.y = __float2bfloat16(t3 - __bfloat162float(h3));
        *reinterpret_cast<__nv_bfloat162*>(olo + rbase + c)     = lp0;
        *reinterpret_cast<__nv_bfloat162*>(olo + rbase + c + 2) = lp1;
    }
}

// ---------------- fused tail: agg gc13 (+res fb) -> fb,feat_out ; sup3 = feat @ W_out ----
__global__ __launch_bounds__(256) void tail_fused(const float* __restrict__ S,
                                                  const float* __restrict__ bias,
                                                  float* __restrict__ fb,
                                                  float* __restrict__ feat_out,
                                                  const float* __restrict__ W_out,
                                                  float* __restrict__ sup3,
                                                  const int* __restrict__ nidx,
                                                  const float* __restrict__ nval,
                                                  const int* __restrict__ ncnt)
{
    int row = (blockIdx.x * blockDim.x + threadIdx.x) >> 5;
    int lane = threadIdx.x & 31;
    if (row >= NN) return;
    int cnt = ncnt[row];
    const int* ni = nidx + (size_t)row * MAXN;
    const float* nv = nval + (size_t)row * MAXN;
    float acc0 = 0.f, acc1 = 0.f, e0 = 0.f, e1 = 0.f;
    for (int i = 0; i < cnt; i += 4) {
        int4   ji = *reinterpret_cast<const int4*>(ni + i);
        float4 ui = *reinterpret_cast<const float4*>(nv + i);
        const float* s0 = S + (size_t)ji.x * HID;
        const float* s1 = S + (size_t)ji.y * HID;
        const float* s2 = S + (size_t)ji.z * HID;
        const float* s3 = S + (size_t)ji.w * HID;
        acc0 = fmaf(ui.x, s0[lane], acc0);  acc1 = fmaf(ui.x, s0[lane + 32], acc1);
        e0   = fmaf(ui.y, s1[lane], e0);    e1   = fmaf(ui.y, s1[lane + 32], e1);
        acc0 = fmaf(ui.z, s2[lane], acc0);  acc1 = fmaf(ui.z, s2[lane + 32], acc1);
        e0   = fmaf(ui.w, s3[lane], e0);    e1   = fmaf(ui.w, s3[lane + 32], e1);
    }
    acc0 += e0; acc1 += e1;

    float w0s = 0.f, w1s = 0.f, w2s = 0.f;
    size_t rbase = (size_t)row * HID;
    #pragma unroll
    for (int j = 0; j < 6; j++) {
        int c = 32 * j + lane;
        float t = (j == 0) ? acc0 : (j == 1) ? acc1 : S[rbase + c];
        t += bias[c];
        t = fmaxf(t, 0.f);
        t = (fb[rbase + c] + t) * 0.5f;
        fb[rbase + c] = t;
        feat_out[rbase + c] = t;
        w0s = fmaf(t, W_out[c * 3 + 0], w0s);
        w1s = fmaf(t, W_out[c * 3 + 1], w1s);
        w2s = fmaf(t, W_out[c * 3 + 2], w2s);
    }
    #pragma unroll
    for (int d = 16; d; d >>= 1) {
        w0s += __shfl_xor_sync(0xffffffffu, w0s, d);
        w1s += __shfl_xor_sync(0xffffffffu, w1s, d);
        w2s += __shfl_xor_sync(0xffffffffu, w2s, d);
    }
    if (lane == 0) {
        sup3[row * 3 + 0] = w0s;
        sup3[row * 3 + 1] = w1s;
        sup3[row * 3 + 2] = w2s;
    }
}

// ---------------- standalone aggregation (coords) ----------------
__global__ __launch_bounds__(256) void agg_kernel(const float* __restrict__ S,
                                                  const float* __restrict__ bias,
                                                  float* __restrict__ out,
                                                  const int* __restrict__ nidx,
                                                  const float* __restrict__ nval,
                                                  const int* __restrict__ ncnt,
                                                  int n_out, int side)
{
    int warp = (blockIdx.x * blockDim.x + threadIdx.x) >> 5;
    int lane = threadIdx.x & 31;
    if (warp >= NN) return;
    int cnt = ncnt[warp];
    const int* ni = nidx + (size_t)warp * MAXN;
    const float* nv = nval + (size_t)warp * MAXN;
    float acc0 = 0.f;
    for (int i = 0; i < cnt; i++) {
        if (lane < side) acc0 = fmaf(nv[i], S[(size_t)ni[i] * n_out + lane], acc0);
    }
    if (lane < n_out) {
        float t = (lane < side) ? acc0 : S[(size_t)warp * n_out + lane];
        t += bias[lane];
        out[(size_t)warp * n_out + lane] = t;
    }
}

extern "C" void kernel_launch(void* const* d_in, const int* in_sizes, int n_in,
                              void* d_out, int out_size)
{
    const float* features = (const float*)d_in[0];
    const float* adj      = (const float*)d_in[1];
    const float* W1       = (const float*)d_in[2];
    const float* b1       = (const float*)d_in[3];
    const float* W_mid    = (const float*)d_in[4];
    const float* b_mid    = (const float*)d_in[5];
    const float* W_out    = (const float*)d_in[6];
    const float* b_out    = (const float*)d_in[7];
    float* out = (float*)d_out;
    float* coords   = out;
    float* feat_out = out + NN * 3;

    float *sa, *sbuf, *fb, *sup3, *nval;
    __nv_bfloat16 *xhi, *xlo, *whi, *wlo;
    int *nidx, *ncnt;
    cudaGetSymbolAddress((void**)&sa,   g_supA);
    cudaGetSymbolAddress((void**)&sbuf, g_supB);
    cudaGetSymbolAddress((void**)&fb,   g_featbuf);
    cudaGetSymbolAddress((void**)&sup3, g_sup3);
    cudaGetSymbolAddress((void**)&xhi,  g_xhi);
    cudaGetSymbolAddress((void**)&xlo,  g_xlo);
    cudaGetSymbolAddress((void**)&whi,  g_wthi);
    cudaGetSymbolAddress((void**)&wlo,  g_wtlo);
    cudaGetSymbolAddress((void**)&nidx, g_nidx);
    cudaGetSymbolAddress((void**)&nval, g_nval);
    cudaGetSymbolAddress((void**)&ncnt, g_ncnt);

    cudaFuncSetAttribute(gemm_os, cudaFuncAttributeMaxDynamicSharedMemorySize, SMEM_K256);
    cudaFuncSetAttribute(gemm_full, cudaFuncAttributeMaxDynamicSharedMemorySize, GF_SMEM);

    build_csr<<<NN / 8, 256>>>(adj, nidx, nval, ncnt);
    convert_weights<<<(WT_TOTAL + 255) / 256, 256>>>(W1, W_mid, whi, wlo);
    convert_features<<<(NN * INF + 255) / 256, 256>>>(features, xhi, xlo);

    auto woff = [](int i) { return (size_t)192 * 256 + (size_t)i * 192 * 192; };

    dim3 g1(NN / BM, HID / BN);
    gemm_os<<<g1, 256, SMEM_K256>>>(xhi, xlo, whi, wlo, sa);

    agg2<0><<<NN / 8, 256>>>(sa, b1, nullptr, nullptr, xhi, xlo, nidx, nval, ncnt);
    gemm_full<<<NN / 64, 512, GF_SMEM>>>(xhi, xlo, whi + woff(0), wlo + woff(0), sbuf);
    agg2<1><<<NN / 8, 256>>>(sbuf, b_mid + 0, features, fb, xhi, xlo, nidx, nval, ncnt);
    gemm_full<<<NN / 64, 512, GF_SMEM>>>(xhi, xlo, whi + woff(1), wlo + woff(1), sa);

    float* cur = sa; float* nxt = sbuf;
    for (int p = 0; p < 5; p++) {
        int bi = 1 + 2 * p;
        agg2<0><<<NN / 8, 256>>>(cur, b_mid + (size_t)bi * HID, nullptr, nullptr,
                                 xhi, xlo, nidx, nval, ncnt);
        gemm_full<<<NN / 64, 512, GF_SMEM>>>(xhi, xlo, whi + woff(bi + 1), wlo + woff(bi + 1), nxt);
        { float* t = cur; cur = nxt; nxt = t; }
        agg2<2><<<NN / 8, 256>>>(cur, b_mid + (size_t)(bi + 1) * HID, fb, fb,
                                 xhi, xlo, nidx, nval, ncnt);
        gemm_full<<<NN / 64, 512, GF_SMEM>>>(xhi, xlo, whi + woff(bi + 2), wlo + woff(bi + 2), nxt);
        { float* t = cur; cur = nxt; nxt = t; }
    }

    // fused tail: agg gc13 + residual + feat_out + sup3 = feat @ W_out
    tail_fused<<<NN / 8, 256>>>(cur, b_mid + (size_t)11 * HID, fb, feat_out,
                                W_out, sup3, nidx, nval, ncnt);
    // coords = agg(sup3, side=2) + b_out
    agg_kernel<<<NN / 8, 256>>>(sup3, b_out, coords, nidx, nval, ncnt, 3, 2);
}

// round 10
// speedup vs baseline: 1.9736x; 1.0914x over previous
#include <cuda_runtime.h>
#include <cuda_bf16.h>
#include <cstdint>
#include <cstddef>

#define NN   8192
#define HID  192
#define INF  256
#define MAXN 128

__device__ float g_supA[NN * HID];
__device__ float g_supB[NN * HID];
__device__ float g_featbuf[NN * HID];
__device__ float g_sup3[NN * 3];
__device__ __nv_bfloat16 g_xhi[NN * INF];
__device__ __nv_bfloat16 g_xlo[NN * INF];
#define WT_TOTAL (192*256 + 12*192*192)
__device__ __nv_bfloat16 g_wthi[WT_TOTAL];
__device__ __nv_bfloat16 g_wtlo[WT_TOTAL];
__device__ int   g_nidx[NN * MAXN];
__device__ float g_nval[NN * MAXN];
__device__ int   g_ncnt[NN];

__device__ __forceinline__ uint32_t smem_u32(const void* p) {
    uint32_t a;
    asm("{ .reg .u64 t; cvta.to.shared.u64 t, %1; cvt.u32.u64 %0, t; }" : "=r"(a) : "l"(p));
    return a;
}
__device__ __forceinline__ void cp16(uint32_t d, const void* s) {
    asm volatile("cp.async.cg.shared.global [%0], [%1], 16;" :: "r"(d), "l"(s));
}
__device__ __forceinline__ void cp_commit() { asm volatile("cp.async.commit_group;" ::: "memory"); }
template <int N> __device__ __forceinline__ void cp_wait() {
    asm volatile("cp.async.wait_group %0;" :: "n"(N) : "memory");
}
__device__ __forceinline__ void ldmx4(uint32_t* r, uint32_t a) {
    asm volatile("ldmatrix.sync.aligned.m8n8.x4.shared.b16 {%0,%1,%2,%3}, [%4];"
        : "=r"(r[0]), "=r"(r[1]), "=r"(r[2]), "=r"(r[3]) : "r"(a));
}
__device__ __forceinline__ void mma16816(float* d, const uint32_t* a, const uint32_t* b) {
    asm volatile("mma.sync.aligned.m16n8k16.row.col.f32.bf16.bf16.f32 "
        "{%0,%1,%2,%3}, {%4,%5,%6,%7}, {%8,%9}, {%0,%1,%2,%3};"
        : "+f"(d[0]), "+f"(d[1]), "+f"(d[2]), "+f"(d[3])
        : "r"(a[0]), "r"(a[1]), "r"(a[2]), "r"(a[3]), "r"(b[0]), "r"(b[1]));
}
__device__ __forceinline__ void gdc_launch() { asm volatile("griddepcontrol.launch_dependents;"); }
__device__ __forceinline__ void gdc_wait()   { asm volatile("griddepcontrol.wait;" ::: "memory"); }

__device__ __forceinline__ void split_store4(float t0, float t1, float t2, float t3,
                                             __nv_bfloat16* ohi, __nv_bfloat16* olo, size_t idx)
{
    __nv_bfloat16 h0 = __float2bfloat16(t0), h1 = __float2bfloat16(t1);
    __nv_bfloat16 h2 = __float2bfloat16(t2), h3 = __float2bfloat16(t3);
    __nv_bfloat162 a; a.x = h0; a.y = h1;
    __nv_bfloat162 b; b.x = h2; b.y = h3;
    *reinterpret_cast<__nv_bfloat162*>(ohi + idx)     = a;
    *reinterpret_cast<__nv_bfloat162*>(ohi + idx + 2) = b;
    __nv_bfloat162 c, d;
    c.x = __float2bfloat16(t0 - __bfloat162float(h0));
    c.y = __float2bfloat16(t1 - __bfloat162float(h1));
    d.x = __float2bfloat16(t2 - __bfloat162float(h2));
    d.y = __float2bfloat16(t3 - __bfloat162float(h3));
    *reinterpret_cast<__nv_bfloat162*>(olo + idx)     = c;
    *reinterpret_cast<__nv_bfloat162*>(olo + idx + 2) = d;
}

// ---------------- CSR extraction ----------------
__global__ __launch_bounds__(256) void build_csr(const float* __restrict__ adj,
                                                 int* __restrict__ nidx,
                                                 float* __restrict__ nval,
                                                 int* __restrict__ ncnt)
{
    int warp = (blockIdx.x * blockDim.x + threadIdx.x) >> 5;
    int lane = threadIdx.x & 31;
    const float4* row = reinterpret_cast<const float4*>(adj + (size_t)warp * NN);
    int* my_idx = nidx + (size_t)warp * MAXN;
    float* my_val = nval + (size_t)warp * MAXN;
    int count = 0;
    for (int it = 0; it < NN / 128; it++) {
        float4 v = row[it * 32 + lane];
        int c0 = it * 128 + lane * 4;
        int my = (v.x != 0.f) + (v.y != 0.f) + (v.z != 0.f) + (v.w != 0.f);
        int inc = my;
        #pragma unroll
        for (int d = 1; d < 32; d <<= 1) {
            int t = __shfl_up_sync(0xffffffffu, inc, d);
            if (lane >= d) inc += t;
        }
        int total = __shfl_sync(0xffffffffu, inc, 31);
        int pos = count + inc - my;
        if (v.x != 0.f) { if (pos < MAXN) { my_idx[pos] = c0;     my_val[pos] = v.x; } pos++; }
        if (v.y != 0.f) { if (pos < MAXN) { my_idx[pos] = c0 + 1; my_val[pos] = v.y; } pos++; }
        if (v.z != 0.f) { if (pos < MAXN) { my_idx[pos] = c0 + 2; my_val[pos] = v.z; } pos++; }
        if (v.w != 0.f) { if (pos < MAXN) { my_idx[pos] = c0 + 3; my_val[pos] = v.w; } pos++; }
        count += total;
    }
    if (count > MAXN) count = MAXN;
    int padded = (count + 3) & ~3;
    if (padded > MAXN) padded = MAXN;
    for (int s = count + lane; s < padded; s += 32) { my_idx[s] = 0; my_val[s] = 0.f; }
    if (lane == 0) ncnt[warp] = padded;
    gdc_launch();
}

__global__ __launch_bounds__(256) void convert_weights(const float* __restrict__ W1,
                                                       const float* __restrict__ W_mid,
                                                       __nv_bfloat16* __restrict__ whi,
                                                       __nv_bfloat16* __restrict__ wlo)
{
    int idx = blockIdx.x * blockDim.x + threadIdx.x;
    if (idx < WT_TOTAL) {
        float w;
        if (idx < 192 * 256) {
            int n = idx / 256, k = idx % 256;
            w = W1[k * 192 + n];
        } else {
            int rel = idx - 192 * 256;
            int i = rel / (192 * 192), r = rel % (192 * 192);
            int n = r / 192, k = r % 192;
            w = W_mid[(size_t)i * 192 * 192 + k * 192 + n];
        }
        __nv_bfloat16 h = __float2bfloat16(w);
        whi[idx] = h;
        wlo[idx] = __float2bfloat16(w - __bfloat162float(h));
    }
    gdc_launch();
}

__global__ __launch_bounds__(256) void convert_features(const float* __restrict__ f,
                                                        __nv_bfloat16* __restrict__ xhi,
                                                        __nv_bfloat16* __restrict__ xlo)
{
    int idx = blockIdx.x * blockDim.x + threadIdx.x;
    if (idx < NN * INF) {
        float v = f[idx];
        __nv_bfloat16 h = __float2bfloat16(v);
        xhi[idx] = h;
        xlo[idx] = __float2bfloat16(v - __bfloat162float(h));
    }
    gdc_launch();
}

// ---------------- gc1 GEMM: K=256, BM=BN=64, PDL ----------------
#define BM 64
#define BN 64
__global__ void __launch_bounds__(256, 1)
gemm_os(const __nv_bfloat16* __restrict__ Xh, const __nv_bfloat16* __restrict__ Xl,
        const __nv_bfloat16* __restrict__ Wh, const __nv_bfloat16* __restrict__ Wl,
        float* __restrict__ S)
{
    constexpr int KK = 256, ASTR = KK * 2 + 16, SLAB = BM * ASTR;
    extern __shared__ char smem[];
    uint32_t sb = smem_u32(smem);
    const uint32_t sAH = sb, sAL = sb + SLAB, sBH = sb + 2 * SLAB, sBL = sb + 3 * SLAB;
    int tid = threadIdx.x;
    int m0 = blockIdx.x * BM, n0 = blockIdx.y * BN;
    int w = tid >> 5, lane = tid & 31;
    int wm = (w & 3) * 16, wn = (w >> 2) * 32;

    // weights pre-wait (independent of predecessor)
    #pragma unroll
    for (int v = tid; v < BM * 32; v += 256) {
        int row = v >> 5, seg = v & 31;
        uint32_t so = row * ASTR + seg * 16;
        size_t gb = (size_t)(n0 + row) * KK + seg * 8;
        cp16(sBH + so, Wh + gb);
        cp16(sBL + so, Wl + gb);
    }
    cp_commit();
    gdc_wait();
    // A in 2 chunks, post-wait
    #pragma unroll
    for (int ch = 0; ch < 2; ch++) {
        #pragma unroll
        for (int v = tid; v < BM * 16; v += 256) {
            int row = v >> 4, seg = v & 15;
            uint32_t so = row * ASTR + (ch * 16 + seg) * 16;
            size_t ga = (size_t)(m0 + row) * KK + ch * 128 + seg * 8;
            cp16(sAH + so, Xh + ga);
            cp16(sAL + so, Xl + ga);
        }
        cp_commit();
    }

    float acc[4][4];
    #pragma unroll
    for (int nt = 0; nt < 4; nt++)
        #pragma unroll
        for (int q = 0; q < 4; q++) acc[nt][q] = 0.f;

    uint32_t aoff = (wm + (lane & 15)) * ASTR + (lane >> 4) * 16;
    uint32_t boff0 = (wn + (lane & 7) + ((lane >> 4) << 3)) * ASTR + (((lane >> 3) & 1) * 16);
    uint32_t boff1 = boff0 + 16 * ASTR;

    auto compute_range = [&](int k0, int k1) {
        #pragma unroll
        for (int ks = k0; ks < k1; ks++) {
            uint32_t ko = ks * 32;
            uint32_t ah[4], al[4], bh[2][4], bl[2][4];
            ldmx4(ah, sAH + aoff + ko);
            ldmx4(al, sAL + aoff + ko);
            ldmx4(bh[0], sBH + boff0 + ko);
            ldmx4(bl[0], sBL + boff0 + ko);
            ldmx4(bh[1], sBH + boff1 + ko);
            ldmx4(bl[1], sBL + boff1 + ko);
            #pragma unroll
            for (int nt = 0; nt < 4; nt++) {
                const uint32_t* b2h = &bh[nt >> 1][(nt & 1) * 2];
                const uint32_t* b2l = &bl[nt >> 1][(nt & 1) * 2];
                mma16816(acc[nt], ah, b2h);
                mma16816(acc[nt], ah, b2l);
                mma16816(acc[nt], al, b2h);
            }
        }
    };
    cp_wait<1>(); __syncthreads();
    compute_range(0, 8);
    cp_wait<0>(); __syncthreads();
    compute_range(8, 16);

    int rb = m0 + wm + (lane >> 2);
    int cb = n0 + wn + (lane & 3) * 2;
    #pragma unroll
    for (int nt = 0; nt < 4; nt++) {
        int cc = cb + nt * 8;
        *reinterpret_cast<float2*>(&S[(size_t)rb * HID + cc]) = make_float2(acc[nt][0], acc[nt][1]);
        *reinterpret_cast<float2*>(&S[(size_t)(rb + 8) * HID + cc]) = make_float2(acc[nt][2], acc[nt][3]);
    }
    gdc_launch();
}
#define SMEM_K256 (4 * BM * (256 * 2 + 16))

// ---------------- mid GEMM: BM=64, BN=192, K=192, 512 thr, PDL ----------------
#define GF_ASTR 400
#define GF_ASLAB (64 * GF_ASTR)
#define GF_BSLAB (192 * GF_ASTR)
#define GF_SMEM (2 * GF_ASLAB + 2 * GF_BSLAB)

__global__ void __launch_bounds__(512, 1)
gemm_full(const __nv_bfloat16* __restrict__ Xh, const __nv_bfloat16* __restrict__ Xl,
          const __nv_bfloat16* __restrict__ Wh, const __nv_bfloat16* __restrict__ Wl,
          float* __restrict__ S)
{
    extern __shared__ char smem[];
    uint32_t sb = smem_u32(smem);
    const uint32_t sAH = sb, sAL = sb + GF_ASLAB;
    const uint32_t sBH = sb + 2 * GF_ASLAB, sBL = sb + 2 * GF_ASLAB + GF_BSLAB;
    int tid = threadIdx.x;
    int m0 = blockIdx.x * 64;
    int w = tid >> 5, lane = tid & 31;
    int wm = (w & 3) * 16, wn = (w >> 2) * 48;

    // full weight tile pre-wait
    #pragma unroll
    for (int v = tid; v < 192 * 24; v += 512) {
        int row = v / 24, seg = v % 24;
        uint32_t so = row * GF_ASTR + seg * 16;
        size_t g = (size_t)row * 192 + seg * 8;
        cp16(sBH + so, Wh + g);
        cp16(sBL + so, Wl + g);
    }
    cp_commit();
    gdc_wait();
    #pragma unroll
    for (int ch = 0; ch < 2; ch++) {
        #pragma unroll
        for (int v = tid; v < 64 * 12; v += 512) {
            int row = v / 12, seg = v % 12;
            uint32_t so = row * GF_ASTR + (ch * 12 + seg) * 16;
            size_t g = (size_t)(m0 + row) * 192 + ch * 96 + seg * 8;
            cp16(sAH + so, Xh + g);
            cp16(sAL + so, Xl + g);
        }
        cp_commit();
    }

    float acc[6][4];
    #pragma unroll
    for (int nt = 0; nt < 6; nt++)
        #pragma unroll
        for (int q = 0; q < 4; q++) acc[nt][q] = 0.f;

    uint32_t aoff = (wm + (lane & 15)) * GF_ASTR + (lane >> 4) * 16;
    uint32_t bbase = (wn + (lane & 7) + ((lane >> 4) << 3)) * GF_ASTR + (((lane >> 3) & 1) * 16);

    auto compute_range = [&](int k0, int k1) {
        #pragma unroll
        for (int ks = k0; ks < k1; ks++) {
            uint32_t ko = ks * 32;
            uint32_t ah[4], al[4], bh[3][4], bl[3][4];
            ldmx4(ah, sAH + aoff + ko);
            ldmx4(al, sAL + aoff + ko);
            #pragma unroll
            for (int p = 0; p < 3; p++) {
                uint32_t bo = bbase + p * 16 * GF_ASTR + ko;
                ldmx4(bh[p], sBH + bo);
                ldmx4(bl[p], sBL + bo);
            }
            #pragma unroll
            for (int nt = 0; nt < 6; nt++) {
                const uint32_t* b2h = &bh[nt >> 1][(nt & 1) * 2];
                const uint32_t* b2l = &bl[nt >> 1][(nt & 1) * 2];
                mma16816(acc[nt], ah, b2h);
                mma16816(acc[nt], ah, b2l);
                mma16816(acc[nt], al, b2h);
            }
        }
    };
    cp_wait<1>(); __syncthreads();
    compute_range(0, 6);
    cp_wait<0>(); __syncthreads();
    compute_range(6, 12);

    int rb = m0 + wm + (lane >> 2);
    int cb = wn + (lane & 3) * 2;
    #pragma unroll
    for (int nt = 0; nt < 6; nt++) {
        int cc = cb + nt * 8;
        *reinterpret_cast<float2*>(&S[(size_t)rb * HID + cc]) = make_float2(acc[nt][0], acc[nt][1]);
        *reinterpret_cast<float2*>(&S[(size_t)(rb + 8) * HID + cc]) = make_float2(acc[nt][2], acc[nt][3]);
    }
    gdc_launch();
}

// ---------------- aggregation: float4 gathers, PDL ----------------
template <int MODE>
__global__ __launch_bounds__(256) void agg2(const float* __restrict__ S,
                                            const float* __restrict__ bias,
                                            const float* __restrict__ resptr,
                                            float* __restrict__ fbout,
                                            __nv_bfloat16* __restrict__ ohi,
                                            __nv_bfloat16* __restrict__ olo,
                                            const int* __restrict__ nidx,
                                            const float* __restrict__ nval,
                                            const int* __restrict__ ncnt)
{
    gdc_wait();
    int row = (blockIdx.x * blockDim.x + threadIdx.x) >> 5;
    int lane = threadIdx.x & 31;
    int half = lane >> 4, sl = lane & 15;
    int cnt = ncnt[row];
    const int* ni = nidx + (size_t)row * MAXN;
    const float* nv = nval + (size_t)row * MAXN;

    float a0 = 0.f, a1 = 0.f, a2 = 0.f, a3 = 0.f;
    float b0 = 0.f, b1 = 0.f, b2 = 0.f, b3 = 0.f;
    for (int i = 0; i < cnt; i += 4) {
        int4   ji = *reinterpret_cast<const int4*>(ni + i);
        float4 wv = *reinterpret_cast<const float4*>(nv + i);
        int   nA = half ? ji.y : ji.x;  float wA = half ? wv.y : wv.x;
        int   nB = half ? ji.w : ji.z;  float wB = half ? wv.w : wv.z;
        float4 vA = *reinterpret_cast<const float4*>(S + (size_t)nA * HID + 4 * sl);
        float4 vB = *reinterpret_cast<const float4*>(S + (size_t)nB * HID + 4 * sl);
        a0 = fmaf(wA, vA.x, a0); a1 = fmaf(wA, vA.y, a1);
        a2 = fmaf(wA, vA.z, a2); a3 = fmaf(wA, vA.w, a3);
        b0 = fmaf(wB, vB.x, b0); b1 = fmaf(wB, vB.y, b1);
        b2 = fmaf(wB, vB.z, b2); b3 = fmaf(wB, vB.w, b3);
    }
    a0 += b0; a1 += b1; a2 += b2; a3 += b3;
    a0 += __shfl_xor_sync(0xffffffffu, a0, 16);
    a1 += __shfl_xor_sync(0xffffffffu, a1, 16);
    a2 += __shfl_xor_sync(0xffffffffu, a2, 16);
    a3 += __shfl_xor_sync(0xffffffffu, a3, 16);

    size_t rbase = (size_t)row * HID;

    if (lane < 16) {
        int c = 4 * sl;
        float4 bs = *reinterpret_cast<const float4*>(bias + c);
        float t0 = fmaxf(a0 + bs.x, 0.f), t1 = fmaxf(a1 + bs.y, 0.f);
        float t2 = fmaxf(a2 + bs.z, 0.f), t3 = fmaxf(a3 + bs.w, 0.f);
        if (MODE == 1) {
            float4 rv = *reinterpret_cast<const float4*>(resptr + (size_t)row * INF + c);
            t0 = (rv.x + t0) * 0.5f; t1 = (rv.y + t1) * 0.5f;
            t2 = (rv.z + t2) * 0.5f; t3 = (rv.w + t3) * 0.5f;
        }
        if (MODE == 2) {
            float4 rv = *reinterpret_cast<const float4*>(resptr + rbase + c);
            t0 = (rv.x + t0) * 0.5f; t1 = (rv.y + t1) * 0.5f;
            t2 = (rv.z + t2) * 0.5f; t3 = (rv.w + t3) * 0.5f;
        }
        if (MODE >= 1)
            *reinterpret_cast<float4*>(fbout + rbase + c) = make_float4(t0, t1, t2, t3);
        split_store4(t0, t1, t2, t3, ohi, olo, rbase + c);
    }
    {
        int c = 64 + 4 * lane;
        float4 sv = *reinterpret_cast<const float4*>(S + rbase + c);
        float4 bs = *reinterpret_cast<const float4*>(bias + c);
        float t0 = fmaxf(sv.x + bs.x, 0.f), t1 = fmaxf(sv.y + bs.y, 0.f);
        float t2 = fmaxf(sv.z + bs.z, 0.f), t3 = fmaxf(sv.w + bs.w, 0.f);
        if (MODE == 1) {
            float4 rv = *reinterpret_cast<const float4*>(resptr + (size_t)row * INF + c);
            t0 = (rv.x + t0) * 0.5f; t1 = (rv.y + t1) * 0.5f;
            t2 = (rv.z + t2) * 0.5f; t3 = (rv.w + t3) * 0.5f;
        }
        if (MODE == 2) {
            float4 rv = *reinterpret_cast<const float4*>(resptr + rbase + c);
            t0 = (rv.x + t0) * 0.5f; t1 = (rv.y + t1) * 0.5f;
            t2 = (rv.z + t2) * 0.5f; t3 = (rv.w + t3) * 0.5f;
        }
        if (MODE >= 1)
            *reinterpret_cast<float4*>(fbout + rbase + c) = make_float4(t0, t1, t2, t3);
        split_store4(t0, t1, t2, t3, ohi, olo, rbase + c);
    }
    gdc_launch();
}

// ---------------- fused tail (gc13 + feat @ W_out), PDL ----------------
__global__ __launch_bounds__(256) void tail_fused(const float* __restrict__ S,
                                                  const float* __restrict__ bias,
                                                  float* __restrict__ fb,
                                                  float* __restrict__ feat_out,
                                                  const float* __restrict__ W_out,
                                                  float* __restrict__ sup3,
                                                  const int* __restrict__ nidx,
                                                  const float* __restrict__ nval,
                                                  const int* __restrict__ ncnt)
{
    gdc_wait();
    int row = (blockIdx.x * blockDim.x + threadIdx.x) >> 5;
    int lane = threadIdx.x & 31;
    int cnt = ncnt[row];
    const int* ni = nidx + (size_t)row * MAXN;
    const float* nv = nval + (size_t)row * MAXN;
    float acc0 = 0.f, acc1 = 0.f, e0 = 0.f, e1 = 0.f;
    for (int i = 0; i < cnt; i += 4) {
        int4   ji = *reinterpret_cast<const int4*>(ni + i);
        float4 ui = *reinterpret_cast<const float4*>(nv + i);
        const float* s0 = S + (size_t)ji.x * HID;
        const float* s1 = S + (size_t)ji.y * HID;
        const float* s2 = S + (size_t)ji.z * HID;
        const float* s3 = S + (size_t)ji.w * HID;
        acc0 = fmaf(ui.x, s0[lane], acc0);  acc1 = fmaf(ui.x, s0[lane + 32], acc1);
        e0   = fmaf(ui.y, s1[lane], e0);    e1   = fmaf(ui.y, s1[lane + 32], e1);
        acc0 = fmaf(ui.z, s2[lane], acc0);  acc1 = fmaf(ui.z, s2[lane + 32], acc1);
        e0   = fmaf(ui.w, s3[lane], e0);    e1   = fmaf(ui.w, s3[lane + 32], e1);
    }
    acc0 += e0; acc1 += e1;

    float w0s = 0.f, w1s = 0.f, w2s = 0.f;
    size_t rbase = (size_t)row * HID;
    #pragma unroll
    for (int j = 0; j < 6; j++) {
        int c = 32 * j + lane;
        float t = (j == 0) ? acc0 : (j == 1) ? acc1 : S[rbase + c];
        t += bias[c];
        t = fmaxf(t, 0.f);
        t = (fb[rbase + c] + t) * 0.5f;
        fb[rbase + c] = t;
        feat_out[rbase + c] = t;
        w0s = fmaf(t, W_out[c * 3 + 0], w0s);
        w1s = fmaf(t, W_out[c * 3 + 1], w1s);
        w2s = fmaf(t, W_out[c * 3 + 2], w2s);
    }
    #pragma unroll
    for (int d = 16; d; d >>= 1) {
        w0s += __shfl_xor_sync(0xffffffffu, w0s, d);
        w1s += __shfl_xor_sync(0xffffffffu, w1s, d);
        w2s += __shfl_xor_sync(0xffffffffu, w2s, d);
    }
    if (lane == 0) {
        sup3[row * 3 + 0] = w0s;
        sup3[row * 3 + 1] = w1s;
        sup3[row * 3 + 2] = w2s;
    }
    gdc_launch();
}

// ---------------- coords, PDL ----------------
__global__ __launch_bounds__(256) void agg_coords(const float* __restrict__ S,
                                                  const float* __restrict__ bias,
                                                  float* __restrict__ out,
                                                  const int* __restrict__ nidx,
                                                  const float* __restrict__ nval,
                                                  const int* __restrict__ ncnt)
{
    gdc_wait();
    int warp = (blockIdx.x * blockDim.x + threadIdx.x) >> 5;
    int lane = threadIdx.x & 31;
    int cnt = ncnt[warp];
    const int* ni = nidx + (size_t)warp * MAXN;
    const float* nv = nval + (size_t)warp * MAXN;
    float acc0 = 0.f;
    for (int i = 0; i < cnt; i++) {
        if (lane < 2) acc0 = fmaf(nv[i], S[(size_t)ni[i] * 3 + lane], acc0);
    }
    if (lane < 3) {
        float t = (lane < 2) ? acc0 : S[(size_t)warp * 3 + lane];
        out[(size_t)warp * 3 + lane] = t + bias[lane];
    }
}

// ---------------- host PDL launcher ----------------
template <typename F, typename... Args>
static inline void pdl(F fn, dim3 g, dim3 b, size_t sm, Args... args)
{
    cudaLaunchConfig_t cfg = {};
    cfg.gridDim = g; cfg.blockDim = b; cfg.dynamicSmemBytes = sm; cfg.stream = 0;
    cudaLaunchAttribute at;
    at.id = cudaLaunchAttributeProgrammaticStreamSerialization;
    at.val.programmaticStreamSerializationAllowed = 1;
    cfg.attrs = &at; cfg.numAttrs = 1;
    cudaLaunchKernelEx(&cfg, fn, args...);
}

extern "C" void kernel_launch(void* const* d_in, const int* in_sizes, int n_in,
                              void* d_out, int out_size)
{
    const float* features = (const float*)d_in[0];
    const float* adj      = (const float*)d_in[1];
    const float* W1       = (const float*)d_in[2];
    const float* b1       = (const float*)d_in[3];
    const float* W_mid    = (const float*)d_in[4];
    const float* b_mid    = (const float*)d_in[5];
    const float* W_out    = (const float*)d_in[6];
    const float* b_out    = (const float*)d_in[7];
    float* out = (float*)d_out;
    float* coords   = out;
    float* feat_out = out + NN * 3;

    float *sa, *sbuf, *fb, *sup3, *nval;
    __nv_bfloat16 *xhi, *xlo, *whi, *wlo;
    int *nidx, *ncnt;
    cudaGetSymbolAddress((void**)&sa,   g_supA);
    cudaGetSymbolAddress((void**)&sbuf, g_supB);
    cudaGetSymbolAddress((void**)&fb,   g_featbuf);
    cudaGetSymbolAddress((void**)&sup3, g_sup3);
    cudaGetSymbolAddress((void**)&xhi,  g_xhi);
    cudaGetSymbolAddress((void**)&xlo,  g_xlo);
    cudaGetSymbolAddress((void**)&whi,  g_wthi);
    cudaGetSymbolAddress((void**)&wlo,  g_wtlo);
    cudaGetSymbolAddress((void**)&nidx, g_nidx);
    cudaGetSymbolAddress((void**)&nval, g_nval);
    cudaGetSymbolAddress((void**)&ncnt, g_ncnt);

    cudaFuncSetAttribute(gemm_os, cudaFuncAttributeMaxDynamicSharedMemorySize, SMEM_K256);
    cudaFuncSetAttribute(gemm_full, cudaFuncAttributeMaxDynamicSharedMemorySize, GF_SMEM);

    build_csr<<<NN / 8, 256>>>(adj, nidx, nval, ncnt);
    pdl(convert_weights, dim3((WT_TOTAL + 255) / 256), dim3(256), 0, W1, W_mid, whi, wlo);
    pdl(convert_features, dim3((NN * INF + 255) / 256), dim3(256), 0, features, xhi, xlo);

    auto woff = [](int i) { return (size_t)192 * 256 + (size_t)i * 192 * 192; };

    pdl(gemm_os, dim3(NN / BM, HID / BN), dim3(256), (size_t)SMEM_K256,
        (const __nv_bfloat16*)xhi, (const __nv_bfloat16*)xlo,
        (const __nv_bfloat16*)whi, (const __nv_bfloat16*)wlo, sa);

    pdl(agg2<0>, dim3(NN / 8), dim3(256), (size_t)0,
        (const float*)sa, b1, (const float*)nullptr, (float*)nullptr,
        xhi, xlo, (const int*)nidx, (const float*)nval, (const int*)ncnt);
    pdl(gemm_full, dim3(NN / 64), dim3(512), (size_t)GF_SMEM,
        (const __nv_bfloat16*)xhi, (const __nv_bfloat16*)xlo,
        (const __nv_bfloat16*)(whi + woff(0)), (const __nv_bfloat16*)(wlo + woff(0)), sbuf);
    pdl(agg2<1>, dim3(NN / 8), dim3(256), (size_t)0,
        (const float*)sbuf, (const float*)(b_mid + 0), features, fb,
        xhi, xlo, (const int*)nidx, (const float*)nval, (const int*)ncnt);
    pdl(gemm_full, dim3(NN / 64), dim3(512), (size_t)GF_SMEM,
        (const __nv_bfloat16*)xhi, (const __nv_bfloat16*)xlo,
        (const __nv_bfloat16*)(whi + woff(1)), (const __nv_bfloat16*)(wlo + woff(1)), sa);

    float* cur = sa; float* nxt = sbuf;
    for (int p = 0; p < 5; p++) {
        int bi = 1 + 2 * p;
        pdl(agg2<0>, dim3(NN / 8), dim3(256), (size_t)0,
            (const float*)cur, (const float*)(b_mid + (size_t)bi * HID),
            (const float*)nullptr, (float*)nullptr,
            xhi, xlo, (const int*)nidx, (const float*)nval, (const int*)ncnt);
        pdl(gemm_full, dim3(NN / 64), dim3(512), (size_t)GF_SMEM,
            (const __nv_bfloat16*)xhi, (const __nv_bfloat16*)xlo,
            (const __nv_bfloat16*)(whi + woff(bi + 1)), (const __nv_bfloat16*)(wlo + woff(bi + 1)), nxt);
        { float* t = cur; cur = nxt; nxt = t; }
        pdl(agg2<2>, dim3(NN / 8), dim3(256), (size_t)0,
            (const float*)cur, (const float*)(b_mid + (size_t)(bi + 1) * HID),
            (const float*)fb, fb,
            xhi, xlo, (const int*)nidx, (const float*)nval, (const int*)ncnt);
        pdl(gemm_full, dim3(NN / 64), dim3(512), (size_t)GF_SMEM,
            (const __nv_bfloat16*)xhi, (const __nv_bfloat16*)xlo,
            (const __nv_bfloat16*)(whi + woff(bi + 2)), (const __nv_bfloat16*)(wlo + woff(bi + 2)), nxt);
        { float* t = cur; cur = nxt; nxt = t; }
    }

    pdl(tail_fused, dim3(NN / 8), dim3(256), (size_t)0,
        (const float*)cur, (const float*)(b_mid + (size_t)11 * HID), fb, feat_out,
        W_out, sup3, (const int*)nidx, (const float*)nval, (const int*)ncnt);
    pdl(agg_coords, dim3(NN / 8), dim3(256), (size_t)0,
        (const float*)sup3, b_out, coords,
        (const int*)nidx, (const float*)nval, (const int*)ncnt);
}